// round 1
// baseline (speedup 1.0000x reference)
#include <cuda_runtime.h>
#include <math.h>

#define NN   1024
#define SS   64
#define DD   256
#define HH   4
#define HDIM 64
#define EE   4096
#define ROWS (NN*SS)   // 65536

// -------- scratch (allocation-free: device globals) --------
__device__ float g_xn [ROWS*DD];
__device__ float g_q  [ROWS*DD];
__device__ float g_k  [ROWS*DD];
__device__ float g_v  [ROWS*DD];
__device__ float g_ctx[ROWS*DD];

// ---------------- zero the context accumulator ----------------
__global__ void zero_ctx_kernel() {
    size_t n4 = (size_t)ROWS * DD / 4;
    float4 z = make_float4(0.f, 0.f, 0.f, 0.f);
    for (size_t i = (size_t)blockIdx.x * blockDim.x + threadIdx.x; i < n4;
         i += (size_t)gridDim.x * blockDim.x)
        ((float4*)g_ctx)[i] = z;
}

// ---------------- LayerNorm: one warp per 256-wide row ----------------
__global__ __launch_bounds__(256) void ln_kernel(
    const float* __restrict__ x, const float* __restrict__ w, const float* __restrict__ b) {
    int row  = blockIdx.x * 8 + (threadIdx.x >> 5);
    int lane = threadIdx.x & 31;
    const float4* xr = (const float4*)(x + (size_t)row * DD);
    float4 v0 = xr[lane];
    float4 v1 = xr[32 + lane];
    float s = v0.x + v0.y + v0.z + v0.w + v1.x + v1.y + v1.z + v1.w;
    #pragma unroll
    for (int o = 16; o; o >>= 1) s += __shfl_xor_sync(0xffffffffu, s, o);
    float mu = s * (1.0f / DD);
    float d0 = v0.x - mu, d1 = v0.y - mu, d2 = v0.z - mu, d3 = v0.w - mu;
    float d4 = v1.x - mu, d5 = v1.y - mu, d6 = v1.z - mu, d7 = v1.w - mu;
    float ss = d0*d0 + d1*d1 + d2*d2 + d3*d3 + d4*d4 + d5*d5 + d6*d6 + d7*d7;
    #pragma unroll
    for (int o = 16; o; o >>= 1) ss += __shfl_xor_sync(0xffffffffu, ss, o);
    float inv = rsqrtf(ss * (1.0f / DD) + 1e-5f);
    float4 w0 = ((const float4*)w)[lane], w1 = ((const float4*)w)[32 + lane];
    float4 b0 = ((const float4*)b)[lane], b1 = ((const float4*)b)[32 + lane];
    float4 o0 = make_float4(d0*inv*w0.x + b0.x, d1*inv*w0.y + b0.y,
                            d2*inv*w0.z + b0.z, d3*inv*w0.w + b0.w);
    float4 o1 = make_float4(d4*inv*w1.x + b1.x, d5*inv*w1.y + b1.y,
                            d6*inv*w1.z + b1.z, d7*inv*w1.w + b1.w);
    float4* outr = (float4*)(g_xn + (size_t)row * DD);
    outr[lane]      = o0;
    outr[32 + lane] = o1;
}

// ---------------- QKV projection: 64x64x16 register-tiled SGEMM ----------------
// grid (1024, 4, 3); z selects {q,k,v}
__global__ __launch_bounds__(256) void qkv_gemm_kernel(
    const float* __restrict__ wq, const float* __restrict__ bqp,
    const float* __restrict__ wk, const float* __restrict__ bkp,
    const float* __restrict__ wv, const float* __restrict__ bvp) {
    const float* B; const float* bias; float* C;
    if (blockIdx.z == 0)      { B = wq; bias = bqp; C = g_q; }
    else if (blockIdx.z == 1) { B = wk; bias = bkp; C = g_k; }
    else                      { B = wv; bias = bvp; C = g_v; }
    const float* A = g_xn;
    int m0 = blockIdx.x * 64, n0 = blockIdx.y * 64;
    int tid = threadIdx.x, tx = tid & 15, ty = tid >> 4;
    __shared__ float As[16 * 65];   // transposed [k][m], padded
    __shared__ float Bs[16 * 64];   // [k][n]
    float acc[4][4] = {};
    int rowA = tid >> 2, c4A = tid & 3;
    int rowB = tid >> 4, c4B = tid & 15;
    for (int k0 = 0; k0 < DD; k0 += 16) {
        float4 a  = *(const float4*)(A + (size_t)(m0 + rowA) * DD + k0 + c4A * 4);
        float4 bb = *(const float4*)(B + (size_t)(k0 + rowB) * DD + n0 + c4B * 4);
        As[(c4A*4 + 0)*65 + rowA] = a.x;
        As[(c4A*4 + 1)*65 + rowA] = a.y;
        As[(c4A*4 + 2)*65 + rowA] = a.z;
        As[(c4A*4 + 3)*65 + rowA] = a.w;
        *(float4*)&Bs[rowB*64 + c4B*4] = bb;
        __syncthreads();
        #pragma unroll
        for (int kk = 0; kk < 16; kk++) {
            float a0 = As[kk*65 + ty*4 + 0];
            float a1 = As[kk*65 + ty*4 + 1];
            float a2 = As[kk*65 + ty*4 + 2];
            float a3 = As[kk*65 + ty*4 + 3];
            float4 b4 = *(float4*)&Bs[kk*64 + tx*4];
            acc[0][0] += a0*b4.x; acc[0][1] += a0*b4.y; acc[0][2] += a0*b4.z; acc[0][3] += a0*b4.w;
            acc[1][0] += a1*b4.x; acc[1][1] += a1*b4.y; acc[1][2] += a1*b4.z; acc[1][3] += a1*b4.w;
            acc[2][0] += a2*b4.x; acc[2][1] += a2*b4.y; acc[2][2] += a2*b4.z; acc[2][3] += a2*b4.w;
            acc[3][0] += a3*b4.x; acc[3][1] += a3*b4.y; acc[3][2] += a3*b4.z; acc[3][3] += a3*b4.w;
        }
        __syncthreads();
    }
    float4 bb = *(const float4*)(bias + n0 + tx*4);
    #pragma unroll
    for (int i = 0; i < 4; i++) {
        size_t m = (size_t)(m0 + ty*4 + i);
        float4 r = make_float4(acc[i][0] + bb.x, acc[i][1] + bb.y,
                               acc[i][2] + bb.z, acc[i][3] + bb.w);
        *(float4*)(C + m * DD + n0 + tx*4) = r;
    }
}

// ---------------- per-(edge, head) attention ----------------
// grid EE*HH blocks of 256 threads; dynamic smem = (3*64*65 + 128) floats
__global__ __launch_bounds__(256) void attn_kernel(
    const long long* __restrict__ ei, const long long* __restrict__ et,
    const float* __restrict__ etw, const float* __restrict__ masks) {
    extern __shared__ float sm[];
    float* qs  = sm;                  // 64*65
    float* ks  = sm + 64*65;          // 64*65
    float* vs  = sm + 2*64*65;        // 64*65
    float* kmv = sm + 3*64*65;        // 64
    float* qmv = kmv + 64;            // 64

    int e   = blockIdx.x >> 2;
    int h   = blockIdx.x & 3;
    int tid = threadIdx.x;

    // detect int64 vs int32 edge buffers (JAX x64 config dependent)
    bool is64 = true;
    #pragma unroll
    for (int i = 0; i < 16; i++) {
        long long v = ei[i];
        if (v < 0 || v >= NN) { is64 = false; break; }
    }
    const int* ei32 = (const int*)ei;
    const int* et32 = (const int*)et;
    int src = is64 ? (int)ei[e]      : ei32[e];
    int dst = is64 ? (int)ei[EE + e] : ei32[EE + e];
    int tt  = is64 ? (int)et[e]      : et32[e];
    float xw = etw[tt - 1];
    float sp = (xw > 20.f) ? xw : log1pf(__expf(xw));
    float ew = fminf(fmaxf(sp, 1e-6f), 1e6f);

    const float* qb = g_q + ((size_t)src * SS) * DD + h * HDIM;
    const float* kb = g_k + ((size_t)dst * SS) * DD + h * HDIM;
    const float* vb = g_v + ((size_t)dst * SS) * DD + h * HDIM;
    for (int i = tid; i < 64 * 16; i += 256) {
        int row = i >> 4, c4 = i & 15;
        float4 a  = *(const float4*)(qb + (size_t)row * DD + c4 * 4);
        float4 bk4 = *(const float4*)(kb + (size_t)row * DD + c4 * 4);
        float4 cv = *(const float4*)(vb + (size_t)row * DD + c4 * 4);
        int o = row * 65 + c4 * 4;
        qs[o+0] = a.x;  qs[o+1] = a.y;  qs[o+2] = a.z;  qs[o+3] = a.w;
        ks[o+0] = bk4.x; ks[o+1] = bk4.y; ks[o+2] = bk4.z; ks[o+3] = bk4.w;
        vs[o+0] = cv.x; vs[o+1] = cv.y; vs[o+2] = cv.z; vs[o+3] = cv.w;
    }
    if (tid < 64) {
        kmv[tid] = masks[(size_t)dst * SS + tid];
        qmv[tid] = masks[(size_t)src * SS + tid];
    }
    __syncthreads();

    int tx = tid & 15, ty = tid >> 4;
    int q0 = ty * 4, c0 = tx * 4;

    // scores = q @ k^T / 8 + ew, masked by key mask
    float acc[4][4] = {};
    #pragma unroll 4
    for (int d = 0; d < 64; d++) {
        float a0 = qs[(q0+0)*65 + d];
        float a1 = qs[(q0+1)*65 + d];
        float a2 = qs[(q0+2)*65 + d];
        float a3 = qs[(q0+3)*65 + d];
        float b0 = ks[(c0+0)*65 + d];
        float b1 = ks[(c0+1)*65 + d];
        float b2 = ks[(c0+2)*65 + d];
        float b3 = ks[(c0+3)*65 + d];
        acc[0][0] += a0*b0; acc[0][1] += a0*b1; acc[0][2] += a0*b2; acc[0][3] += a0*b3;
        acc[1][0] += a1*b0; acc[1][1] += a1*b1; acc[1][2] += a1*b2; acc[1][3] += a1*b3;
        acc[2][0] += a2*b0; acc[2][1] += a2*b1; acc[2][2] += a2*b2; acc[2][3] += a2*b3;
        acc[3][0] += a3*b0; acc[3][1] += a3*b1; acc[3][2] += a3*b2; acc[3][3] += a3*b3;
    }
    float km[4] = { kmv[c0], kmv[c0+1], kmv[c0+2], kmv[c0+3] };
    float p[4][4];
    #pragma unroll
    for (int i = 0; i < 4; i++)
        #pragma unroll
        for (int j = 0; j < 4; j++) {
            float sc = acc[i][j] * 0.125f + ew;
            p[i][j] = (km[j] > 0.f) ? sc : -1e30f;
        }

    // row softmax across the 16 tx-lanes (half-warp butterfly)
    #pragma unroll
    for (int i = 0; i < 4; i++) {
        float m = fmaxf(fmaxf(p[i][0], p[i][1]), fmaxf(p[i][2], p[i][3]));
        #pragma unroll
        for (int o = 1; o < 16; o <<= 1) m = fmaxf(m, __shfl_xor_sync(0xffffffffu, m, o));
        float s = 0.f;
        #pragma unroll
        for (int j = 0; j < 4; j++) { float ex = __expf(p[i][j] - m); p[i][j] = ex; s += ex; }
        #pragma unroll
        for (int o = 1; o < 16; o <<= 1) s += __shfl_xor_sync(0xffffffffu, s, o);
        float invs = 1.0f / s;
        #pragma unroll
        for (int j = 0; j < 4; j++) p[i][j] = p[i][j] * invs * km[j];
    }

    // stage attention weights in qs (q tile no longer needed)
    __syncthreads();
    #pragma unroll
    for (int i = 0; i < 4; i++)
        #pragma unroll
        for (int j = 0; j < 4; j++)
            qs[(q0+i)*65 + c0 + j] = p[i][j];
    __syncthreads();

    // ctx = attn @ v   (tx now indexes head-dim output)
    float o4[4][4] = {};
    #pragma unroll 4
    for (int kj = 0; kj < 64; kj++) {
        float a0 = qs[(q0+0)*65 + kj];
        float a1 = qs[(q0+1)*65 + kj];
        float a2 = qs[(q0+2)*65 + kj];
        float a3 = qs[(q0+3)*65 + kj];
        float b0 = vs[kj*65 + c0 + 0];
        float b1 = vs[kj*65 + c0 + 1];
        float b2 = vs[kj*65 + c0 + 2];
        float b3 = vs[kj*65 + c0 + 3];
        o4[0][0] += a0*b0; o4[0][1] += a0*b1; o4[0][2] += a0*b2; o4[0][3] += a0*b3;
        o4[1][0] += a1*b0; o4[1][1] += a1*b1; o4[1][2] += a1*b2; o4[1][3] += a1*b3;
        o4[2][0] += a2*b0; o4[2][1] += a2*b1; o4[2][2] += a2*b2; o4[2][3] += a2*b3;
        o4[3][0] += a3*b0; o4[3][1] += a3*b1; o4[3][2] += a3*b2; o4[3][3] += a3*b3;
    }
    float* ob = g_ctx + ((size_t)src * SS) * DD + h * HDIM;
    #pragma unroll
    for (int i = 0; i < 4; i++) {
        float qm = qmv[q0 + i];
        if (qm > 0.f) {
            #pragma unroll
            for (int j = 0; j < 4; j++)
                atomicAdd(ob + (size_t)(q0+i) * DD + c0 + j, o4[i][j] * qm);
        }
    }
}

// ---------------- output projection + residual + mask ----------------
__global__ __launch_bounds__(256) void out_gemm_kernel(
    const float* __restrict__ wo, const float* __restrict__ bo,
    const float* __restrict__ nf, const float* __restrict__ masks,
    float* __restrict__ out) {
    const float* A = g_ctx;
    int m0 = blockIdx.x * 64, n0 = blockIdx.y * 64;
    int tid = threadIdx.x, tx = tid & 15, ty = tid >> 4;
    __shared__ float As[16 * 65];
    __shared__ float Bs[16 * 64];
    float acc[4][4] = {};
    int rowA = tid >> 2, c4A = tid & 3;
    int rowB = tid >> 4, c4B = tid & 15;
    for (int k0 = 0; k0 < DD; k0 += 16) {
        float4 a  = *(const float4*)(A + (size_t)(m0 + rowA) * DD + k0 + c4A * 4);
        float4 bb = *(const float4*)(wo + (size_t)(k0 + rowB) * DD + n0 + c4B * 4);
        As[(c4A*4 + 0)*65 + rowA] = a.x;
        As[(c4A*4 + 1)*65 + rowA] = a.y;
        As[(c4A*4 + 2)*65 + rowA] = a.z;
        As[(c4A*4 + 3)*65 + rowA] = a.w;
        *(float4*)&Bs[rowB*64 + c4B*4] = bb;
        __syncthreads();
        #pragma unroll
        for (int kk = 0; kk < 16; kk++) {
            float a0 = As[kk*65 + ty*4 + 0];
            float a1 = As[kk*65 + ty*4 + 1];
            float a2 = As[kk*65 + ty*4 + 2];
            float a3 = As[kk*65 + ty*4 + 3];
            float4 b4 = *(float4*)&Bs[kk*64 + tx*4];
            acc[0][0] += a0*b4.x; acc[0][1] += a0*b4.y; acc[0][2] += a0*b4.z; acc[0][3] += a0*b4.w;
            acc[1][0] += a1*b4.x; acc[1][1] += a1*b4.y; acc[1][2] += a1*b4.z; acc[1][3] += a1*b4.w;
            acc[2][0] += a2*b4.x; acc[2][1] += a2*b4.y; acc[2][2] += a2*b4.z; acc[2][3] += a2*b4.w;
            acc[3][0] += a3*b4.x; acc[3][1] += a3*b4.y; acc[3][2] += a3*b4.z; acc[3][3] += a3*b4.w;
        }
        __syncthreads();
    }
    float4 bb = *(const float4*)(bo + n0 + tx*4);
    #pragma unroll
    for (int i = 0; i < 4; i++) {
        size_t m = (size_t)(m0 + ty*4 + i);
        float mk = masks[m];
        float4 r = *(const float4*)(nf + m * DD + n0 + tx*4);
        float4 w4 = make_float4((acc[i][0] + bb.x + r.x) * mk,
                                (acc[i][1] + bb.y + r.y) * mk,
                                (acc[i][2] + bb.z + r.z) * mk,
                                (acc[i][3] + bb.w + r.w) * mk);
        *(float4*)(out + m * DD + n0 + tx*4) = w4;
    }
}

extern "C" void kernel_launch(void* const* d_in, const int* in_sizes, int n_in,
                              void* d_out, int out_size) {
    const float* nf    = (const float*)d_in[0];
    const float* masks = (const float*)d_in[1];
    const float* lnw   = (const float*)d_in[2];
    const float* lnb   = (const float*)d_in[3];
    const float* wq    = (const float*)d_in[4];
    const float* bq    = (const float*)d_in[5];
    const float* wk    = (const float*)d_in[6];
    const float* bk    = (const float*)d_in[7];
    const float* wv    = (const float*)d_in[8];
    const float* bv    = (const float*)d_in[9];
    const float* wo    = (const float*)d_in[10];
    const float* bo    = (const float*)d_in[11];
    const float* etw   = (const float*)d_in[12];
    const long long* ei = (const long long*)d_in[13];
    const long long* et = (const long long*)d_in[14];
    float* out = (float*)d_out;

    zero_ctx_kernel<<<4096, 256>>>();
    ln_kernel<<<ROWS / 8, 256>>>(nf, lnw, lnb);
    qkv_gemm_kernel<<<dim3(ROWS / 64, DD / 64, 3), 256>>>(wq, bq, wk, bk, wv, bv);

    int attn_smem = (3 * 64 * 65 + 128) * (int)sizeof(float);  // 50432 B
    cudaFuncSetAttribute(attn_kernel, cudaFuncAttributeMaxDynamicSharedMemorySize, attn_smem);
    attn_kernel<<<EE * HH, 256, attn_smem>>>(ei, et, etw, masks);

    out_gemm_kernel<<<dim3(ROWS / 64, DD / 64), 256>>>(wo, bo, nf, masks, out);
}

// round 3
// speedup vs baseline: 2.2219x; 2.2219x over previous
#include <cuda_runtime.h>
#include <cuda_bf16.h>
#include <math.h>
#include <stdint.h>

#define NN   1024
#define SS   64
#define DD   256
#define HH   4
#define HDIM 64
#define EE   4096
#define ROWS (NN*SS)   // 65536

// -------- scratch (allocation-free: device globals) --------
__device__ __nv_bfloat16 g_xn_hi[ROWS*DD];
__device__ __nv_bfloat16 g_xn_lo[ROWS*DD];
__device__ __nv_bfloat16 g_q_hi [ROWS*DD];   // pre-scaled by 1/8
__device__ __nv_bfloat16 g_q_lo [ROWS*DD];
__device__ __nv_bfloat16 g_k_hi [ROWS*DD];
__device__ __nv_bfloat16 g_k_lo [ROWS*DD];
__device__ __nv_bfloat16 g_v_hi [ROWS*DD];
__device__ __nv_bfloat16 g_v_lo [ROWS*DD];
__device__ float g_ctx[ROWS*DD];
__device__ __nv_bfloat16 g_ctx_hi[ROWS*DD];
__device__ __nv_bfloat16 g_ctx_lo[ROWS*DD];
__device__ __nv_bfloat16 g_wt_hi[4*DD*DD];   // transposed weights [n][k] (q,k,v,o)
__device__ __nv_bfloat16 g_wt_lo[4*DD*DD];

// ================= HMMA helper =================
__device__ __forceinline__ void mma_bf16(float c[4],
    uint32_t a0, uint32_t a1, uint32_t a2, uint32_t a3, uint32_t b0, uint32_t b1) {
    asm volatile(
        "mma.sync.aligned.m16n8k16.row.col.f32.bf16.bf16.f32 "
        "{%0,%1,%2,%3}, {%4,%5,%6,%7}, {%8,%9}, {%0,%1,%2,%3};"
        : "+f"(c[0]), "+f"(c[1]), "+f"(c[2]), "+f"(c[3])
        : "r"(a0), "r"(a1), "r"(a2), "r"(a3), "r"(b0), "r"(b1));
}

__device__ __forceinline__ uint32_t packbf(float x, float y) {
    __nv_bfloat162 t = __floats2bfloat162_rn(x, y);
    return *(uint32_t*)&t;
}
__device__ __forceinline__ float bflo(float x) {
    return x - __bfloat162float(__float2bfloat16(x));
}

// ---------------- zero the context accumulator ----------------
__global__ void zero_ctx_kernel() {
    size_t n4 = (size_t)ROWS * DD / 4;
    float4 z = make_float4(0.f, 0.f, 0.f, 0.f);
    for (size_t i = (size_t)blockIdx.x * blockDim.x + threadIdx.x; i < n4;
         i += (size_t)gridDim.x * blockDim.x)
        ((float4*)g_ctx)[i] = z;
}

__device__ __forceinline__ void split4(float4 v, uint32_t& hi2a, uint32_t& hi2b,
                                       uint32_t& lo2a, uint32_t& lo2b) {
    hi2a = packbf(v.x, v.y); hi2b = packbf(v.z, v.w);
    lo2a = packbf(bflo(v.x), bflo(v.y)); lo2b = packbf(bflo(v.z), bflo(v.w));
}

// ---------------- LayerNorm -> bf16 hi/lo split ----------------
__global__ __launch_bounds__(256) void ln_kernel(
    const float* __restrict__ x, const float* __restrict__ w, const float* __restrict__ b) {
    int row  = blockIdx.x * 8 + (threadIdx.x >> 5);
    int lane = threadIdx.x & 31;
    const float4* xr = (const float4*)(x + (size_t)row * DD);
    float4 v0 = xr[lane];
    float4 v1 = xr[32 + lane];
    float s = v0.x + v0.y + v0.z + v0.w + v1.x + v1.y + v1.z + v1.w;
    #pragma unroll
    for (int o = 16; o; o >>= 1) s += __shfl_xor_sync(0xffffffffu, s, o);
    float mu = s * (1.0f / DD);
    float d0 = v0.x - mu, d1 = v0.y - mu, d2 = v0.z - mu, d3 = v0.w - mu;
    float d4 = v1.x - mu, d5 = v1.y - mu, d6 = v1.z - mu, d7 = v1.w - mu;
    float ss = d0*d0 + d1*d1 + d2*d2 + d3*d3 + d4*d4 + d5*d5 + d6*d6 + d7*d7;
    #pragma unroll
    for (int o = 16; o; o >>= 1) ss += __shfl_xor_sync(0xffffffffu, ss, o);
    float inv = rsqrtf(ss * (1.0f / DD) + 1e-5f);
    float4 w0 = ((const float4*)w)[lane], w1 = ((const float4*)w)[32 + lane];
    float4 b0 = ((const float4*)b)[lane], b1 = ((const float4*)b)[32 + lane];
    float4 o0 = make_float4(d0*inv*w0.x + b0.x, d1*inv*w0.y + b0.y,
                            d2*inv*w0.z + b0.z, d3*inv*w0.w + b0.w);
    float4 o1 = make_float4(d4*inv*w1.x + b1.x, d5*inv*w1.y + b1.y,
                            d6*inv*w1.z + b1.z, d7*inv*w1.w + b1.w);
    size_t base = (size_t)row * DD;
    uint32_t ha, hb, la, lb;
    split4(o0, ha, hb, la, lb);
    *(uint2*)(g_xn_hi + base + lane*4) = make_uint2(ha, hb);
    *(uint2*)(g_xn_lo + base + lane*4) = make_uint2(la, lb);
    split4(o1, ha, hb, la, lb);
    *(uint2*)(g_xn_hi + base + 128 + lane*4) = make_uint2(ha, hb);
    *(uint2*)(g_xn_lo + base + 128 + lane*4) = make_uint2(la, lb);
}

// ---------------- weight transpose + bf16 split ----------------
__global__ __launch_bounds__(256) void wconv_kernel(
    const float* __restrict__ wq, const float* __restrict__ wk,
    const float* __restrict__ wv, const float* __restrict__ wo) {
    int n = blockIdx.x, z = blockIdx.y, k = threadIdx.x;
    const float* w = (z == 0) ? wq : (z == 1) ? wk : (z == 2) ? wv : wo;
    float v = w[(size_t)k * DD + n];
    __nv_bfloat16 h = __float2bfloat16(v);
    __nv_bfloat16 l = __float2bfloat16(v - __bfloat162float(h));
    size_t o = (size_t)z * DD * DD + (size_t)n * DD + k;
    g_wt_hi[o] = h;
    g_wt_lo[o] = l;
}

// ---------------- ctx fp32 -> bf16 hi/lo ----------------
__global__ __launch_bounds__(256) void ctxconv_kernel() {
    size_t idx = (size_t)blockIdx.x * 256 + threadIdx.x;
    float4 v = ((const float4*)g_ctx)[idx];
    uint32_t ha, hb, la, lb;
    split4(v, ha, hb, la, lb);
    *(uint2*)(g_ctx_hi + idx * 4) = make_uint2(ha, hb);
    *(uint2*)(g_ctx_lo + idx * 4) = make_uint2(la, lb);
}

// ================= HMMA GEMM mainloop (A row-major, B = Wt[n][k]) =================
// smem layout: AHI(0) ALO(18432) BHI(36864) BLO(55296), each 128x(64 pad to 72) bf16
#define G_AHI 0
#define G_ALO 18432
#define G_BHI 36864
#define G_BLO 55296
#define G_SMEM 73728
#define LDSM(base, idx) (*(const uint32_t*)(sm + (base) + (size_t)(idx) * 2))

__device__ __forceinline__ void gemm_mainloop(
    char* sm, int tid,
    const __nv_bfloat16* aHi, const __nv_bfloat16* aLo, size_t m0,
    const __nv_bfloat16* bHi, const __nv_bfloat16* bLo, size_t n0,
    float c[2][8][4]) {
    int lane = tid & 31, wid = tid >> 5;
    int g = lane >> 2, tg = lane & 3;
    int wm = wid & 3, wn = wid >> 2;
    for (int kc = 0; kc < 4; kc++) {
        __syncthreads();
        #pragma unroll
        for (int it = 0; it < 4; it++) {
            int i = tid + it * 256;
            int row = i >> 3, seg = i & 7;
            int so = (row * 72 + seg * 8) * 2;
            size_t ga = (size_t)(m0 + row) * DD + kc * 64 + seg * 8;
            size_t gb = (size_t)(n0 + row) * DD + kc * 64 + seg * 8;
            *(uint4*)(sm + G_AHI + so) = *(const uint4*)(aHi + ga);
            *(uint4*)(sm + G_ALO + so) = *(const uint4*)(aLo + ga);
            *(uint4*)(sm + G_BHI + so) = *(const uint4*)(bHi + gb);
            *(uint4*)(sm + G_BLO + so) = *(const uint4*)(bLo + gb);
        }
        __syncthreads();
        #pragma unroll
        for (int kt = 0; kt < 4; kt++) {
            int kb = kt * 16 + tg * 2;
            uint32_t ah[2][4], al[2][4];
            #pragma unroll
            for (int mi = 0; mi < 2; mi++) {
                int r = wm * 32 + mi * 16 + g;
                ah[mi][0] = LDSM(G_AHI, r * 72 + kb);
                ah[mi][1] = LDSM(G_AHI, (r + 8) * 72 + kb);
                ah[mi][2] = LDSM(G_AHI, r * 72 + kb + 8);
                ah[mi][3] = LDSM(G_AHI, (r + 8) * 72 + kb + 8);
                al[mi][0] = LDSM(G_ALO, r * 72 + kb);
                al[mi][1] = LDSM(G_ALO, (r + 8) * 72 + kb);
                al[mi][2] = LDSM(G_ALO, r * 72 + kb + 8);
                al[mi][3] = LDSM(G_ALO, (r + 8) * 72 + kb + 8);
            }
            #pragma unroll
            for (int ni = 0; ni < 8; ni++) {
                int n = wn * 64 + ni * 8 + g;
                uint32_t bh0 = LDSM(G_BHI, n * 72 + kb);
                uint32_t bh1 = LDSM(G_BHI, n * 72 + kb + 8);
                uint32_t bl0 = LDSM(G_BLO, n * 72 + kb);
                uint32_t bl1 = LDSM(G_BLO, n * 72 + kb + 8);
                #pragma unroll
                for (int mi = 0; mi < 2; mi++) {
                    mma_bf16(c[mi][ni], ah[mi][0], ah[mi][1], ah[mi][2], ah[mi][3], bh0, bh1);
                    mma_bf16(c[mi][ni], ah[mi][0], ah[mi][1], ah[mi][2], ah[mi][3], bl0, bl1);
                    mma_bf16(c[mi][ni], al[mi][0], al[mi][1], al[mi][2], al[mi][3], bh0, bh1);
                }
            }
        }
    }
}

// ---------------- QKV projection (HMMA) -> bf16 hi/lo outputs ----------------
__global__ __launch_bounds__(256, 2) void qkv_mma_kernel(
    const float* __restrict__ bq, const float* __restrict__ bk, const float* __restrict__ bv) {
    extern __shared__ char sm[];
    int tid = threadIdx.x, lane = tid & 31, wid = tid >> 5;
    int g = lane >> 2, tg = lane & 3;
    int wm = wid & 3, wn = wid >> 2;
    int z = blockIdx.z;
    size_t m0 = (size_t)blockIdx.x * 128, n0 = (size_t)blockIdx.y * 128;
    const float* bias = (z == 0) ? bq : (z == 1) ? bk : bv;
    __nv_bfloat16* oh = (z == 0) ? g_q_hi : (z == 1) ? g_k_hi : g_v_hi;
    __nv_bfloat16* ol = (z == 0) ? g_q_lo : (z == 1) ? g_k_lo : g_v_lo;
    const __nv_bfloat16* Bh = g_wt_hi + (size_t)z * DD * DD;
    const __nv_bfloat16* Bl = g_wt_lo + (size_t)z * DD * DD;
    float scale = (z == 0) ? 0.125f : 1.0f;

    float c[2][8][4] = {};
    gemm_mainloop(sm, tid, g_xn_hi, g_xn_lo, m0, Bh, Bl, n0, c);

    #pragma unroll
    for (int mi = 0; mi < 2; mi++) {
        int rA = (int)m0 + wm * 32 + mi * 16 + g;
        int rB = rA + 8;
        #pragma unroll
        for (int ni = 0; ni < 8; ni++) {
            int n = (int)n0 + wn * 64 + ni * 8 + tg * 2;
            float b0v = bias[n], b1v = bias[n + 1];
            float v0 = (c[mi][ni][0] + b0v) * scale;
            float v1 = (c[mi][ni][1] + b1v) * scale;
            float v2 = (c[mi][ni][2] + b0v) * scale;
            float v3 = (c[mi][ni][3] + b1v) * scale;
            *(uint32_t*)(oh + (size_t)rA * DD + n) = packbf(v0, v1);
            *(uint32_t*)(ol + (size_t)rA * DD + n) = packbf(bflo(v0), bflo(v1));
            *(uint32_t*)(oh + (size_t)rB * DD + n) = packbf(v2, v3);
            *(uint32_t*)(ol + (size_t)rB * DD + n) = packbf(bflo(v2), bflo(v3));
        }
    }
}

// ---------------- output projection + residual + mask (HMMA) ----------------
__global__ __launch_bounds__(256, 2) void out_mma_kernel(
    const float* __restrict__ bo, const float* __restrict__ nf,
    const float* __restrict__ masks, float* __restrict__ out) {
    extern __shared__ char sm[];
    int tid = threadIdx.x, lane = tid & 31, wid = tid >> 5;
    int g = lane >> 2, tg = lane & 3;
    int wm = wid & 3, wn = wid >> 2;
    size_t m0 = (size_t)blockIdx.x * 128, n0 = (size_t)blockIdx.y * 128;
    const __nv_bfloat16* Bh = g_wt_hi + (size_t)3 * DD * DD;
    const __nv_bfloat16* Bl = g_wt_lo + (size_t)3 * DD * DD;

    float c[2][8][4] = {};
    gemm_mainloop(sm, tid, g_ctx_hi, g_ctx_lo, m0, Bh, Bl, n0, c);

    #pragma unroll
    for (int mi = 0; mi < 2; mi++) {
        int rA = (int)m0 + wm * 32 + mi * 16 + g;
        int rB = rA + 8;
        float mkA = masks[rA], mkB = masks[rB];
        #pragma unroll
        for (int ni = 0; ni < 8; ni++) {
            int n = (int)n0 + wn * 64 + ni * 8 + tg * 2;
            float b0v = bo[n], b1v = bo[n + 1];
            float2 resA = *(const float2*)(nf + (size_t)rA * DD + n);
            float2 resB = *(const float2*)(nf + (size_t)rB * DD + n);
            float2 oA = make_float2((c[mi][ni][0] + b0v + resA.x) * mkA,
                                    (c[mi][ni][1] + b1v + resA.y) * mkA);
            float2 oB = make_float2((c[mi][ni][2] + b0v + resB.x) * mkB,
                                    (c[mi][ni][3] + b1v + resB.y) * mkB);
            *(float2*)(out + (size_t)rA * DD + n) = oA;
            *(float2*)(out + (size_t)rB * DD + n) = oB;
        }
    }
}

// ---------------- per-(edge, head) attention on HMMA ----------------
// smem: QH(0) QL KH KL VH VL each 64x72 bf16 (9216B), then kmv/qmv floats
#define A_QH 0
#define A_QL 9216
#define A_KH 18432
#define A_KL 27648
#define A_VH 36864
#define A_VL 46080
#define A_KM 55296
#define A_QM 55552
#define A_SMEM 55808

__global__ __launch_bounds__(128, 4) void attn_mma_kernel(
    const long long* __restrict__ ei, const long long* __restrict__ et,
    const float* __restrict__ etw, const float* __restrict__ masks) {
    extern __shared__ char sm[];
    float* kmv = (float*)(sm + A_KM);
    float* qmv = (float*)(sm + A_QM);

    int e = blockIdx.x >> 2;
    int h = blockIdx.x & 3;
    int tid = threadIdx.x, lane = tid & 31, wid = tid >> 5;
    int g = lane >> 2, tg = lane & 3;

    bool is64 = true;
    #pragma unroll
    for (int i = 0; i < 16; i++) {
        long long v = ei[i];
        if (v < 0 || v >= NN) { is64 = false; break; }
    }
    const int* ei32 = (const int*)ei;
    const int* et32 = (const int*)et;
    int src = is64 ? (int)ei[e]      : ei32[e];
    int dst = is64 ? (int)ei[EE + e] : ei32[EE + e];
    int tt  = is64 ? (int)et[e]      : et32[e];
    float xw = etw[tt - 1];
    float sp = (xw > 20.f) ? xw : log1pf(__expf(xw));
    float ew = fminf(fmaxf(sp, 1e-6f), 1e6f);

    // ---- load q/k (row-major) and v (transposed) hi/lo tiles ----
    size_t qbase = ((size_t)src * SS) * DD + h * HDIM;
    size_t kbase = ((size_t)dst * SS) * DD + h * HDIM;
    for (int i = tid; i < 512; i += 128) {
        int row = i >> 3, seg = i & 7;
        int so = (row * 72 + seg * 8) * 2;
        size_t go = (size_t)row * DD + seg * 8;
        *(uint4*)(sm + A_QH + so) = *(const uint4*)(g_q_hi + qbase + go);
        *(uint4*)(sm + A_QL + so) = *(const uint4*)(g_q_lo + qbase + go);
        *(uint4*)(sm + A_KH + so) = *(const uint4*)(g_k_hi + kbase + go);
        *(uint4*)(sm + A_KL + so) = *(const uint4*)(g_k_lo + kbase + go);
        // v: transpose into [hd][key]
        uint4 vh4 = *(const uint4*)(g_v_hi + kbase + go);
        uint4 vl4 = *(const uint4*)(g_v_lo + kbase + go);
        __nv_bfloat16 th[8], tl[8];
        *(uint4*)th = vh4; *(uint4*)tl = vl4;
        #pragma unroll
        for (int j = 0; j < 8; j++) {
            int hd = seg * 8 + j;
            *(__nv_bfloat16*)(sm + A_VH + (hd * 72 + row) * 2) = th[j];
            *(__nv_bfloat16*)(sm + A_VL + (hd * 72 + row) * 2) = tl[j];
        }
    }
    if (tid < 64) {
        kmv[tid] = masks[(size_t)dst * SS + tid];
        qmv[tid] = masks[(size_t)src * SS + tid];
    }
    __syncthreads();

    int r0 = wid * 16;

    // ---- scores = (q/8) @ k^T + ew ----
    float sc[8][4] = {};
    #pragma unroll
    for (int kt = 0; kt < 4; kt++) {
        int kb = kt * 16 + tg * 2;
        uint32_t ah0 = LDSM(A_QH, (r0 + g) * 72 + kb);
        uint32_t ah1 = LDSM(A_QH, (r0 + g + 8) * 72 + kb);
        uint32_t ah2 = LDSM(A_QH, (r0 + g) * 72 + kb + 8);
        uint32_t ah3 = LDSM(A_QH, (r0 + g + 8) * 72 + kb + 8);
        uint32_t al0 = LDSM(A_QL, (r0 + g) * 72 + kb);
        uint32_t al1 = LDSM(A_QL, (r0 + g + 8) * 72 + kb);
        uint32_t al2 = LDSM(A_QL, (r0 + g) * 72 + kb + 8);
        uint32_t al3 = LDSM(A_QL, (r0 + g + 8) * 72 + kb + 8);
        #pragma unroll
        for (int jn = 0; jn < 8; jn++) {
            int n = jn * 8 + g;
            uint32_t bh0 = LDSM(A_KH, n * 72 + kb);
            uint32_t bh1 = LDSM(A_KH, n * 72 + kb + 8);
            uint32_t bl0 = LDSM(A_KL, n * 72 + kb);
            uint32_t bl1 = LDSM(A_KL, n * 72 + kb + 8);
            mma_bf16(sc[jn], ah0, ah1, ah2, ah3, bh0, bh1);
            mma_bf16(sc[jn], ah0, ah1, ah2, ah3, bl0, bl1);
            mma_bf16(sc[jn], al0, al1, al2, al3, bh0, bh1);
        }
    }

    // ---- bias + mask + softmax (rows g and g+8 of this warp's 16) ----
    float kmr[8][2];
    #pragma unroll
    for (int jn = 0; jn < 8; jn++) {
        int col = jn * 8 + tg * 2;
        kmr[jn][0] = kmv[col];
        kmr[jn][1] = kmv[col + 1];
        sc[jn][0] = (kmr[jn][0] > 0.f) ? sc[jn][0] + ew : -1e30f;
        sc[jn][1] = (kmr[jn][1] > 0.f) ? sc[jn][1] + ew : -1e30f;
        sc[jn][2] = (kmr[jn][0] > 0.f) ? sc[jn][2] + ew : -1e30f;
        sc[jn][3] = (kmr[jn][1] > 0.f) ? sc[jn][3] + ew : -1e30f;
    }
    float mA = -1e30f, mB = -1e30f;
    #pragma unroll
    for (int jn = 0; jn < 8; jn++) {
        mA = fmaxf(mA, fmaxf(sc[jn][0], sc[jn][1]));
        mB = fmaxf(mB, fmaxf(sc[jn][2], sc[jn][3]));
    }
    mA = fmaxf(mA, __shfl_xor_sync(0xffffffffu, mA, 1));
    mA = fmaxf(mA, __shfl_xor_sync(0xffffffffu, mA, 2));
    mB = fmaxf(mB, __shfl_xor_sync(0xffffffffu, mB, 1));
    mB = fmaxf(mB, __shfl_xor_sync(0xffffffffu, mB, 2));
    float sA = 0.f, sB = 0.f;
    #pragma unroll
    for (int jn = 0; jn < 8; jn++) {
        sc[jn][0] = __expf(sc[jn][0] - mA); sA += sc[jn][0];
        sc[jn][1] = __expf(sc[jn][1] - mA); sA += sc[jn][1];
        sc[jn][2] = __expf(sc[jn][2] - mB); sB += sc[jn][2];
        sc[jn][3] = __expf(sc[jn][3] - mB); sB += sc[jn][3];
    }
    sA += __shfl_xor_sync(0xffffffffu, sA, 1);
    sA += __shfl_xor_sync(0xffffffffu, sA, 2);
    sB += __shfl_xor_sync(0xffffffffu, sB, 1);
    sB += __shfl_xor_sync(0xffffffffu, sB, 2);
    float iA = 1.0f / sA, iB = 1.0f / sB;
    #pragma unroll
    for (int jn = 0; jn < 8; jn++) {
        sc[jn][0] *= iA * kmr[jn][0];
        sc[jn][1] *= iA * kmr[jn][1];
        sc[jn][2] *= iB * kmr[jn][0];
        sc[jn][3] *= iB * kmr[jn][1];
    }

    // ---- repack P (C-frag -> A-frag), hi/lo ----
    uint32_t phi[4][4], plo[4][4];
    #pragma unroll
    for (int kt = 0; kt < 4; kt++) {
        int j0 = 2 * kt, j1 = 2 * kt + 1;
        phi[kt][0] = packbf(sc[j0][0], sc[j0][1]);
        phi[kt][1] = packbf(sc[j0][2], sc[j0][3]);
        phi[kt][2] = packbf(sc[j1][0], sc[j1][1]);
        phi[kt][3] = packbf(sc[j1][2], sc[j1][3]);
        plo[kt][0] = packbf(bflo(sc[j0][0]), bflo(sc[j0][1]));
        plo[kt][1] = packbf(bflo(sc[j0][2]), bflo(sc[j0][3]));
        plo[kt][2] = packbf(bflo(sc[j1][0]), bflo(sc[j1][1]));
        plo[kt][3] = packbf(bflo(sc[j1][2]), bflo(sc[j1][3]));
    }

    // ---- ctx = P @ V  (B from transposed V tiles) ----
    float o4[8][4] = {};
    #pragma unroll
    for (int kt = 0; kt < 4; kt++) {
        int kb = kt * 16 + tg * 2;
        #pragma unroll
        for (int jn = 0; jn < 8; jn++) {
            int n = jn * 8 + g;
            uint32_t bh0 = LDSM(A_VH, n * 72 + kb);
            uint32_t bh1 = LDSM(A_VH, n * 72 + kb + 8);
            uint32_t bl0 = LDSM(A_VL, n * 72 + kb);
            uint32_t bl1 = LDSM(A_VL, n * 72 + kb + 8);
            mma_bf16(o4[jn], phi[kt][0], phi[kt][1], phi[kt][2], phi[kt][3], bh0, bh1);
            mma_bf16(o4[jn], phi[kt][0], phi[kt][1], phi[kt][2], phi[kt][3], bl0, bl1);
            mma_bf16(o4[jn], plo[kt][0], plo[kt][1], plo[kt][2], plo[kt][3], bh0, bh1);
        }
    }

    // ---- scatter-add into g_ctx with query mask ----
    int rowA = r0 + g, rowB = r0 + g + 8;
    float qmA = qmv[rowA], qmB = qmv[rowB];
    float* baseA = g_ctx + ((size_t)src * SS + rowA) * DD + h * HDIM;
    float* baseB = g_ctx + ((size_t)src * SS + rowB) * DD + h * HDIM;
    #pragma unroll
    for (int jn = 0; jn < 8; jn++) {
        int col = jn * 8 + tg * 2;
        if (qmA > 0.f) {
            atomicAdd(baseA + col,     o4[jn][0] * qmA);
            atomicAdd(baseA + col + 1, o4[jn][1] * qmA);
        }
        if (qmB > 0.f) {
            atomicAdd(baseB + col,     o4[jn][2] * qmB);
            atomicAdd(baseB + col + 1, o4[jn][3] * qmB);
        }
    }
}

extern "C" void kernel_launch(void* const* d_in, const int* in_sizes, int n_in,
                              void* d_out, int out_size) {
    const float* nf    = (const float*)d_in[0];
    const float* masks = (const float*)d_in[1];
    const float* lnw   = (const float*)d_in[2];
    const float* lnb   = (const float*)d_in[3];
    const float* wq    = (const float*)d_in[4];
    const float* bq    = (const float*)d_in[5];
    const float* wk    = (const float*)d_in[6];
    const float* bk    = (const float*)d_in[7];
    const float* wv    = (const float*)d_in[8];
    const float* bv    = (const float*)d_in[9];
    const float* wo    = (const float*)d_in[10];
    const float* bo    = (const float*)d_in[11];
    const float* etw   = (const float*)d_in[12];
    const long long* ei = (const long long*)d_in[13];
    const long long* et = (const long long*)d_in[14];
    float* out = (float*)d_out;

    cudaFuncSetAttribute(qkv_mma_kernel, cudaFuncAttributeMaxDynamicSharedMemorySize, G_SMEM);
    cudaFuncSetAttribute(out_mma_kernel, cudaFuncAttributeMaxDynamicSharedMemorySize, G_SMEM);
    cudaFuncSetAttribute(attn_mma_kernel, cudaFuncAttributeMaxDynamicSharedMemorySize, A_SMEM);

    zero_ctx_kernel<<<4096, 256>>>();
    ln_kernel<<<ROWS / 8, 256>>>(nf, lnw, lnb);
    wconv_kernel<<<dim3(DD, 4), 256>>>(wq, wk, wv, wo);
    qkv_mma_kernel<<<dim3(ROWS / 128, DD / 128, 3), 256, G_SMEM>>>(bq, bk, bv);
    attn_mma_kernel<<<EE * HH, 128, A_SMEM>>>(ei, et, etw, masks);
    ctxconv_kernel<<<ROWS * DD / 4 / 256, 256>>>();
    out_mma_kernel<<<dim3(ROWS / 128, DD / 128), 256, G_SMEM>>>(bo, nf, masks, out);
}

// round 4
// speedup vs baseline: 2.6492x; 1.1923x over previous
#include <cuda_runtime.h>
#include <cuda_bf16.h>
#include <math.h>
#include <stdint.h>

#define NN   1024
#define SS   64
#define DD   256
#define HH   4
#define HDIM 64
#define EE   4096
#define ROWS (NN*SS)   // 65536

// -------- scratch (allocation-free: device globals) --------
__device__ __nv_bfloat16 g_xn_hi[ROWS*DD];
__device__ __nv_bfloat16 g_xn_lo[ROWS*DD];
__device__ __nv_bfloat16 g_q_hi [ROWS*DD];   // pre-scaled by 1/8
__device__ __nv_bfloat16 g_q_lo [ROWS*DD];
__device__ __nv_bfloat16 g_k_hi [ROWS*DD];
__device__ __nv_bfloat16 g_k_lo [ROWS*DD];
__device__ __nv_bfloat16 g_v_hi [ROWS*DD];
__device__ __nv_bfloat16 g_v_lo [ROWS*DD];
__device__ float g_ctx[ROWS*DD];
__device__ __nv_bfloat16 g_wt_hi[4*DD*DD];   // transposed weights [n][k] (q,k,v,o)
__device__ __nv_bfloat16 g_wt_lo[4*DD*DD];

// ================= MMA / ldmatrix helpers =================
__device__ __forceinline__ void mma_bf16(float c[4],
    uint32_t a0, uint32_t a1, uint32_t a2, uint32_t a3, uint32_t b0, uint32_t b1) {
    asm volatile(
        "mma.sync.aligned.m16n8k16.row.col.f32.bf16.bf16.f32 "
        "{%0,%1,%2,%3}, {%4,%5,%6,%7}, {%8,%9}, {%0,%1,%2,%3};"
        : "+f"(c[0]), "+f"(c[1]), "+f"(c[2]), "+f"(c[3])
        : "r"(a0), "r"(a1), "r"(a2), "r"(a3), "r"(b0), "r"(b1));
}
__device__ __forceinline__ void ldsm4(uint32_t a, uint32_t& r0, uint32_t& r1,
                                      uint32_t& r2, uint32_t& r3) {
    asm volatile("ldmatrix.sync.aligned.m8n8.x4.shared.b16 {%0,%1,%2,%3}, [%4];"
        : "=r"(r0), "=r"(r1), "=r"(r2), "=r"(r3) : "r"(a));
}
__device__ __forceinline__ uint32_t smem_u32(const void* p) {
    uint32_t r;
    asm("{ .reg .u64 t; cvta.to.shared.u64 t, %1; cvt.u32.u64 %0, t; }" : "=r"(r) : "l"(p));
    return r;
}
__device__ __forceinline__ uint32_t packbf(float x, float y) {
    __nv_bfloat162 t = __floats2bfloat162_rn(x, y);
    return *(uint32_t*)&t;
}
__device__ __forceinline__ float bflo(float x) {
    return x - __bfloat162float(__float2bfloat16(x));
}
__device__ __forceinline__ void split4(float4 v, uint32_t& hi2a, uint32_t& hi2b,
                                       uint32_t& lo2a, uint32_t& lo2b) {
    hi2a = packbf(v.x, v.y); hi2b = packbf(v.z, v.w);
    lo2a = packbf(bflo(v.x), bflo(v.y)); lo2b = packbf(bflo(v.z), bflo(v.w));
}

// ---------------- zero the context accumulator ----------------
__global__ void zero_ctx_kernel() {
    size_t n4 = (size_t)ROWS * DD / 4;
    float4 z = make_float4(0.f, 0.f, 0.f, 0.f);
    for (size_t i = (size_t)blockIdx.x * blockDim.x + threadIdx.x; i < n4;
         i += (size_t)gridDim.x * blockDim.x)
        ((float4*)g_ctx)[i] = z;
}

// ---------------- LayerNorm -> bf16 hi/lo split ----------------
__global__ __launch_bounds__(256) void ln_kernel(
    const float* __restrict__ x, const float* __restrict__ w, const float* __restrict__ b) {
    int row  = blockIdx.x * 8 + (threadIdx.x >> 5);
    int lane = threadIdx.x & 31;
    const float4* xr = (const float4*)(x + (size_t)row * DD);
    float4 v0 = xr[lane];
    float4 v1 = xr[32 + lane];
    float s = v0.x + v0.y + v0.z + v0.w + v1.x + v1.y + v1.z + v1.w;
    #pragma unroll
    for (int o = 16; o; o >>= 1) s += __shfl_xor_sync(0xffffffffu, s, o);
    float mu = s * (1.0f / DD);
    float d0 = v0.x - mu, d1 = v0.y - mu, d2 = v0.z - mu, d3 = v0.w - mu;
    float d4 = v1.x - mu, d5 = v1.y - mu, d6 = v1.z - mu, d7 = v1.w - mu;
    float ss = d0*d0 + d1*d1 + d2*d2 + d3*d3 + d4*d4 + d5*d5 + d6*d6 + d7*d7;
    #pragma unroll
    for (int o = 16; o; o >>= 1) ss += __shfl_xor_sync(0xffffffffu, ss, o);
    float inv = rsqrtf(ss * (1.0f / DD) + 1e-5f);
    float4 w0 = ((const float4*)w)[lane], w1 = ((const float4*)w)[32 + lane];
    float4 b0 = ((const float4*)b)[lane], b1 = ((const float4*)b)[32 + lane];
    float4 o0 = make_float4(d0*inv*w0.x + b0.x, d1*inv*w0.y + b0.y,
                            d2*inv*w0.z + b0.z, d3*inv*w0.w + b0.w);
    float4 o1 = make_float4(d4*inv*w1.x + b1.x, d5*inv*w1.y + b1.y,
                            d6*inv*w1.z + b1.z, d7*inv*w1.w + b1.w);
    size_t base = (size_t)row * DD;
    uint32_t ha, hb, la, lb;
    split4(o0, ha, hb, la, lb);
    *(uint2*)(g_xn_hi + base + lane*4) = make_uint2(ha, hb);
    *(uint2*)(g_xn_lo + base + lane*4) = make_uint2(la, lb);
    split4(o1, ha, hb, la, lb);
    *(uint2*)(g_xn_hi + base + 128 + lane*4) = make_uint2(ha, hb);
    *(uint2*)(g_xn_lo + base + 128 + lane*4) = make_uint2(la, lb);
}

// ---------------- weight transpose + bf16 split ----------------
__global__ __launch_bounds__(256) void wconv_kernel(
    const float* __restrict__ wq, const float* __restrict__ wk,
    const float* __restrict__ wv, const float* __restrict__ wo) {
    int n = blockIdx.x, z = blockIdx.y, k = threadIdx.x;
    const float* w = (z == 0) ? wq : (z == 1) ? wk : (z == 2) ? wv : wo;
    float v = w[(size_t)k * DD + n];
    __nv_bfloat16 h = __float2bfloat16(v);
    __nv_bfloat16 l = __float2bfloat16(v - __bfloat162float(h));
    size_t o = (size_t)z * DD * DD + (size_t)n * DD + k;
    g_wt_hi[o] = h;
    g_wt_lo[o] = l;
}

// ================= HMMA GEMM mainloop (ldmatrix fragments) =================
// smem: AHI(0) ALO(18432) BHI(36864) BLO(55296), each 128x(64 pad to 72) bf16
#define G_AHI 0
#define G_ALO 18432
#define G_BHI 36864
#define G_BLO 55296
#define G_SMEM 73728

template<bool AFP32>
__device__ __forceinline__ void gemm_mainloop(
    char* sm, int tid,
    const void* aHiP, const void* aLoP, size_t m0,
    const __nv_bfloat16* bHi, const __nv_bfloat16* bLo, size_t n0,
    float c[2][8][4]) {
    uint32_t sbu = smem_u32(sm);
    int lane = tid & 31, wid = tid >> 5;
    int wm = wid & 3, wn = wid >> 2;
    uint32_t aoff = (uint32_t)(((lane & 15) * 72 + (lane >> 4) * 8) * 2);
    uint32_t boff = (uint32_t)((((lane & 7) + ((lane >> 4) << 3)) * 72 + (lane & 8)) * 2);
    uint32_t aB0 = sbu + G_AHI + aoff + (uint32_t)(wm * 32) * 144;
    uint32_t aB1 = aB0 + 16 * 144;
    uint32_t bB  = sbu + G_BHI + boff + (uint32_t)(wn * 64) * 144;
    const uint32_t ALO_D = G_ALO - G_AHI, BLO_D = G_BLO - G_BHI;

    for (int kc = 0; kc < 4; kc++) {
        __syncthreads();
        #pragma unroll
        for (int it = 0; it < 4; it++) {
            int i = tid + it * 256;
            int row = i >> 3, seg = i & 7;
            int so = (row * 72 + seg * 8) * 2;
            size_t gb = (size_t)(n0 + row) * DD + kc * 64 + seg * 8;
            if (AFP32) {
                const float* aF = (const float*)aHiP;
                size_t ga = (size_t)(m0 + row) * DD + kc * 64 + seg * 8;
                float4 f0 = *(const float4*)(aF + ga);
                float4 f1 = *(const float4*)(aF + ga + 4);
                uint32_t ha, hb, la, lb;
                split4(f0, ha, hb, la, lb);
                uint32_t hc, hd, lc, ld;
                split4(f1, hc, hd, lc, ld);
                *(uint4*)(sm + G_AHI + so) = make_uint4(ha, hb, hc, hd);
                *(uint4*)(sm + G_ALO + so) = make_uint4(la, lb, lc, ld);
            } else {
                const __nv_bfloat16* aHi = (const __nv_bfloat16*)aHiP;
                const __nv_bfloat16* aLo = (const __nv_bfloat16*)aLoP;
                size_t ga = (size_t)(m0 + row) * DD + kc * 64 + seg * 8;
                *(uint4*)(sm + G_AHI + so) = *(const uint4*)(aHi + ga);
                *(uint4*)(sm + G_ALO + so) = *(const uint4*)(aLo + ga);
            }
            *(uint4*)(sm + G_BHI + so) = *(const uint4*)(bHi + gb);
            *(uint4*)(sm + G_BLO + so) = *(const uint4*)(bLo + gb);
        }
        __syncthreads();
        #pragma unroll
        for (int kt = 0; kt < 4; kt++) {
            uint32_t ko = (uint32_t)(kt * 32);
            uint32_t ah[2][4], al[2][4];
            ldsm4(aB0 + ko,         ah[0][0], ah[0][1], ah[0][2], ah[0][3]);
            ldsm4(aB1 + ko,         ah[1][0], ah[1][1], ah[1][2], ah[1][3]);
            ldsm4(aB0 + ALO_D + ko, al[0][0], al[0][1], al[0][2], al[0][3]);
            ldsm4(aB1 + ALO_D + ko, al[1][0], al[1][1], al[1][2], al[1][3]);
            #pragma unroll
            for (int jp = 0; jp < 4; jp++) {
                uint32_t bh[4], bl[4];
                ldsm4(bB + jp * 2304 + ko,         bh[0], bh[1], bh[2], bh[3]);
                ldsm4(bB + BLO_D + jp * 2304 + ko, bl[0], bl[1], bl[2], bl[3]);
                #pragma unroll
                for (int mi = 0; mi < 2; mi++) {
                    mma_bf16(c[mi][2*jp],   ah[mi][0], ah[mi][1], ah[mi][2], ah[mi][3], bh[0], bh[1]);
                    mma_bf16(c[mi][2*jp],   ah[mi][0], ah[mi][1], ah[mi][2], ah[mi][3], bl[0], bl[1]);
                    mma_bf16(c[mi][2*jp],   al[mi][0], al[mi][1], al[mi][2], al[mi][3], bh[0], bh[1]);
                    mma_bf16(c[mi][2*jp+1], ah[mi][0], ah[mi][1], ah[mi][2], ah[mi][3], bh[2], bh[3]);
                    mma_bf16(c[mi][2*jp+1], ah[mi][0], ah[mi][1], ah[mi][2], ah[mi][3], bl[2], bl[3]);
                    mma_bf16(c[mi][2*jp+1], al[mi][0], al[mi][1], al[mi][2], al[mi][3], bh[2], bh[3]);
                }
            }
        }
    }
}

// ---------------- QKV projection (HMMA) -> bf16 hi/lo outputs ----------------
__global__ __launch_bounds__(256, 2) void qkv_mma_kernel(
    const float* __restrict__ bq, const float* __restrict__ bk, const float* __restrict__ bv) {
    extern __shared__ char sm[];
    int tid = threadIdx.x, lane = tid & 31, wid = tid >> 5;
    int g = lane >> 2, tg = lane & 3;
    int wm = wid & 3, wn = wid >> 2;
    int z = blockIdx.z;
    size_t m0 = (size_t)blockIdx.x * 128, n0 = (size_t)blockIdx.y * 128;
    const float* bias = (z == 0) ? bq : (z == 1) ? bk : bv;
    __nv_bfloat16* oh = (z == 0) ? g_q_hi : (z == 1) ? g_k_hi : g_v_hi;
    __nv_bfloat16* ol = (z == 0) ? g_q_lo : (z == 1) ? g_k_lo : g_v_lo;
    const __nv_bfloat16* Bh = g_wt_hi + (size_t)z * DD * DD;
    const __nv_bfloat16* Bl = g_wt_lo + (size_t)z * DD * DD;
    float scale = (z == 0) ? 0.125f : 1.0f;

    float c[2][8][4] = {};
    gemm_mainloop<false>(sm, tid, g_xn_hi, g_xn_lo, m0, Bh, Bl, n0, c);

    #pragma unroll
    for (int mi = 0; mi < 2; mi++) {
        int rA = (int)m0 + wm * 32 + mi * 16 + g;
        int rB = rA + 8;
        #pragma unroll
        for (int ni = 0; ni < 8; ni++) {
            int n = (int)n0 + wn * 64 + ni * 8 + tg * 2;
            float b0v = bias[n], b1v = bias[n + 1];
            float v0 = (c[mi][ni][0] + b0v) * scale;
            float v1 = (c[mi][ni][1] + b1v) * scale;
            float v2 = (c[mi][ni][2] + b0v) * scale;
            float v3 = (c[mi][ni][3] + b1v) * scale;
            *(uint32_t*)(oh + (size_t)rA * DD + n) = packbf(v0, v1);
            *(uint32_t*)(ol + (size_t)rA * DD + n) = packbf(bflo(v0), bflo(v1));
            *(uint32_t*)(oh + (size_t)rB * DD + n) = packbf(v2, v3);
            *(uint32_t*)(ol + (size_t)rB * DD + n) = packbf(bflo(v2), bflo(v3));
        }
    }
}

// ---------------- output projection + residual + mask (HMMA, fp32-A fused split) ----------------
__global__ __launch_bounds__(256, 2) void out_mma_kernel(
    const float* __restrict__ bo, const float* __restrict__ nf,
    const float* __restrict__ masks, float* __restrict__ out) {
    extern __shared__ char sm[];
    int tid = threadIdx.x, lane = tid & 31, wid = tid >> 5;
    int g = lane >> 2, tg = lane & 3;
    int wm = wid & 3, wn = wid >> 2;
    size_t m0 = (size_t)blockIdx.x * 128, n0 = (size_t)blockIdx.y * 128;
    const __nv_bfloat16* Bh = g_wt_hi + (size_t)3 * DD * DD;
    const __nv_bfloat16* Bl = g_wt_lo + (size_t)3 * DD * DD;

    float c[2][8][4] = {};
    gemm_mainloop<true>(sm, tid, g_ctx, nullptr, m0, Bh, Bl, n0, c);

    #pragma unroll
    for (int mi = 0; mi < 2; mi++) {
        int rA = (int)m0 + wm * 32 + mi * 16 + g;
        int rB = rA + 8;
        float mkA = masks[rA], mkB = masks[rB];
        #pragma unroll
        for (int ni = 0; ni < 8; ni++) {
            int n = (int)n0 + wn * 64 + ni * 8 + tg * 2;
            float b0v = bo[n], b1v = bo[n + 1];
            float2 resA = *(const float2*)(nf + (size_t)rA * DD + n);
            float2 resB = *(const float2*)(nf + (size_t)rB * DD + n);
            float2 oA = make_float2((c[mi][ni][0] + b0v + resA.x) * mkA,
                                    (c[mi][ni][1] + b1v + resA.y) * mkA);
            float2 oB = make_float2((c[mi][ni][2] + b0v + resB.x) * mkB,
                                    (c[mi][ni][3] + b1v + resB.y) * mkB);
            *(float2*)(out + (size_t)rA * DD + n) = oA;
            *(float2*)(out + (size_t)rB * DD + n) = oB;
        }
    }
}

// ---------------- per-(edge, head) attention on HMMA + ldmatrix + mask skipping ----------------
#define A_QH 0
#define A_QL 9216
#define A_KH 18432
#define A_KL 27648
#define A_VH 36864
#define A_VL 46080
#define A_KM 55296
#define A_QM 55552
#define A_SMEM 55808

__global__ __launch_bounds__(128, 4) void attn_mma_kernel(
    const long long* __restrict__ ei, const long long* __restrict__ et,
    const float* __restrict__ etw, const float* __restrict__ masks) {
    extern __shared__ char sm[];
    uint32_t sbu = smem_u32(sm);
    float* kmv = (float*)(sm + A_KM);
    float* qmv = (float*)(sm + A_QM);

    int e = blockIdx.x >> 2;
    int h = blockIdx.x & 3;
    int tid = threadIdx.x, lane = tid & 31, wid = tid >> 5;
    int g = lane >> 2, tg = lane & 3;

    bool is64 = true;
    #pragma unroll
    for (int i = 0; i < 16; i++) {
        long long v = ei[i];
        if (v < 0 || v >= NN) { is64 = false; break; }
    }
    const int* ei32 = (const int*)ei;
    const int* et32 = (const int*)et;
    int src = is64 ? (int)ei[e]      : ei32[e];
    int dst = is64 ? (int)ei[EE + e] : ei32[EE + e];
    int tt  = is64 ? (int)et[e]      : et32[e];
    float xw = etw[tt - 1];
    float sp = (xw > 20.f) ? xw : log1pf(__expf(xw));
    float ew = fminf(fmaxf(sp, 1e-6f), 1e6f);

    // lengths from masks (prefix masks: len = popcount of >0)
    float md0 = masks[(size_t)dst * SS + lane], md1 = masks[(size_t)dst * SS + 32 + lane];
    float ms0 = masks[(size_t)src * SS + lane], ms1 = masks[(size_t)src * SS + 32 + lane];
    int len_dst = __popc(__ballot_sync(0xffffffffu, md0 > 0.f)) +
                  __popc(__ballot_sync(0xffffffffu, md1 > 0.f));
    int len_src = __popc(__ballot_sync(0xffffffffu, ms0 > 0.f)) +
                  __popc(__ballot_sync(0xffffffffu, ms1 > 0.f));
    int lq = (len_src + 15) & ~15;              // q rows to stage
    int lk = (len_dst + 15) & ~15;              // k/v rows to stage
    int jpmax = (((len_dst + 7) >> 3) + 1) >> 1; // QK 16-col pair groups
    int ktmax = (len_dst + 15) >> 4;             // PV k tiles

    // ---- stage q/k (row-major) and v (transposed) hi/lo tiles ----
    size_t qbase = ((size_t)src * SS) * DD + h * HDIM;
    size_t kbase = ((size_t)dst * SS) * DD + h * HDIM;
    for (int i = tid; i < 512; i += 128) {
        int row = i >> 3, seg = i & 7;
        int so = (row * 72 + seg * 8) * 2;
        size_t go = (size_t)row * DD + seg * 8;
        if (row < lq) {
            *(uint4*)(sm + A_QH + so) = *(const uint4*)(g_q_hi + qbase + go);
            *(uint4*)(sm + A_QL + so) = *(const uint4*)(g_q_lo + qbase + go);
        }
        if (row < lk) {
            *(uint4*)(sm + A_KH + so) = *(const uint4*)(g_k_hi + kbase + go);
            *(uint4*)(sm + A_KL + so) = *(const uint4*)(g_k_lo + kbase + go);
            uint4 vh4 = *(const uint4*)(g_v_hi + kbase + go);
            uint4 vl4 = *(const uint4*)(g_v_lo + kbase + go);
            __nv_bfloat16 th[8], tl[8];
            *(uint4*)th = vh4; *(uint4*)tl = vl4;
            #pragma unroll
            for (int j = 0; j < 8; j++) {
                int hd = seg * 8 + j;
                *(__nv_bfloat16*)(sm + A_VH + (hd * 72 + row) * 2) = th[j];
                *(__nv_bfloat16*)(sm + A_VL + (hd * 72 + row) * 2) = tl[j];
            }
        }
    }
    if (tid < 32) { kmv[lane] = md0; kmv[32 + lane] = md1; }
    else if (tid < 64) { qmv[lane] = ms0; qmv[32 + lane] = ms1; }
    __syncthreads();

    int r0 = wid * 16;
    if (r0 >= len_src) return;   // whole-warp skip; no further syncs in kernel

    uint32_t aoff = (uint32_t)(((lane & 15) * 72 + (lane >> 4) * 8) * 2);
    uint32_t boff = (uint32_t)((((lane & 7) + ((lane >> 4) << 3)) * 72 + (lane & 8)) * 2);
    uint32_t qBH = sbu + A_QH + aoff + (uint32_t)r0 * 144;
    uint32_t qBL = qBH + (A_QL - A_QH);
    uint32_t kBH = sbu + A_KH + boff;
    uint32_t kBL = kBH + (A_KL - A_KH);
    uint32_t vBH = sbu + A_VH + boff;
    uint32_t vBL = vBH + (A_VL - A_VH);

    // ---- scores = (q/8) @ k^T ----
    float sc[8][4] = {};
    #pragma unroll
    for (int kt = 0; kt < 4; kt++) {
        uint32_t ko = (uint32_t)(kt * 32);
        uint32_t ah[4], al[4];
        ldsm4(qBH + ko, ah[0], ah[1], ah[2], ah[3]);
        ldsm4(qBL + ko, al[0], al[1], al[2], al[3]);
        for (int jp = 0; jp < jpmax; jp++) {
            uint32_t bh[4], bl[4];
            ldsm4(kBH + jp * 2304 + ko, bh[0], bh[1], bh[2], bh[3]);
            ldsm4(kBL + jp * 2304 + ko, bl[0], bl[1], bl[2], bl[3]);
            mma_bf16(sc[2*jp],   ah[0], ah[1], ah[2], ah[3], bh[0], bh[1]);
            mma_bf16(sc[2*jp],   ah[0], ah[1], ah[2], ah[3], bl[0], bl[1]);
            mma_bf16(sc[2*jp],   al[0], al[1], al[2], al[3], bh[0], bh[1]);
            mma_bf16(sc[2*jp+1], ah[0], ah[1], ah[2], ah[3], bh[2], bh[3]);
            mma_bf16(sc[2*jp+1], ah[0], ah[1], ah[2], ah[3], bl[2], bl[3]);
            mma_bf16(sc[2*jp+1], al[0], al[1], al[2], al[3], bh[2], bh[3]);
        }
    }

    // ---- bias + key mask + softmax ----
    float kmr[8][2];
    #pragma unroll
    for (int jn = 0; jn < 8; jn++) {
        int col = jn * 8 + tg * 2;
        kmr[jn][0] = kmv[col];
        kmr[jn][1] = kmv[col + 1];
        sc[jn][0] = (kmr[jn][0] > 0.f) ? sc[jn][0] + ew : -1e30f;
        sc[jn][1] = (kmr[jn][1] > 0.f) ? sc[jn][1] + ew : -1e30f;
        sc[jn][2] = (kmr[jn][0] > 0.f) ? sc[jn][2] + ew : -1e30f;
        sc[jn][3] = (kmr[jn][1] > 0.f) ? sc[jn][3] + ew : -1e30f;
    }
    float mA = -1e30f, mB = -1e30f;
    #pragma unroll
    for (int jn = 0; jn < 8; jn++) {
        mA = fmaxf(mA, fmaxf(sc[jn][0], sc[jn][1]));
        mB = fmaxf(mB, fmaxf(sc[jn][2], sc[jn][3]));
    }
    mA = fmaxf(mA, __shfl_xor_sync(0xffffffffu, mA, 1));
    mA = fmaxf(mA, __shfl_xor_sync(0xffffffffu, mA, 2));
    mB = fmaxf(mB, __shfl_xor_sync(0xffffffffu, mB, 1));
    mB = fmaxf(mB, __shfl_xor_sync(0xffffffffu, mB, 2));
    float sA = 0.f, sB = 0.f;
    #pragma unroll
    for (int jn = 0; jn < 8; jn++) {
        sc[jn][0] = __expf(sc[jn][0] - mA); sA += sc[jn][0];
        sc[jn][1] = __expf(sc[jn][1] - mA); sA += sc[jn][1];
        sc[jn][2] = __expf(sc[jn][2] - mB); sB += sc[jn][2];
        sc[jn][3] = __expf(sc[jn][3] - mB); sB += sc[jn][3];
    }
    sA += __shfl_xor_sync(0xffffffffu, sA, 1);
    sA += __shfl_xor_sync(0xffffffffu, sA, 2);
    sB += __shfl_xor_sync(0xffffffffu, sB, 1);
    sB += __shfl_xor_sync(0xffffffffu, sB, 2);
    float iA = 1.0f / sA, iB = 1.0f / sB;
    #pragma unroll
    for (int jn = 0; jn < 8; jn++) {
        sc[jn][0] *= iA * kmr[jn][0];
        sc[jn][1] *= iA * kmr[jn][1];
        sc[jn][2] *= iB * kmr[jn][0];
        sc[jn][3] *= iB * kmr[jn][1];
    }

    // ---- repack P (C-frag -> A-frag), hi/lo ----
    uint32_t phi[4][4], plo[4][4];
    #pragma unroll
    for (int kt = 0; kt < 4; kt++) {
        int j0 = 2 * kt, j1 = 2 * kt + 1;
        phi[kt][0] = packbf(sc[j0][0], sc[j0][1]);
        phi[kt][1] = packbf(sc[j0][2], sc[j0][3]);
        phi[kt][2] = packbf(sc[j1][0], sc[j1][1]);
        phi[kt][3] = packbf(sc[j1][2], sc[j1][3]);
        plo[kt][0] = packbf(bflo(sc[j0][0]), bflo(sc[j0][1]));
        plo[kt][1] = packbf(bflo(sc[j0][2]), bflo(sc[j0][3]));
        plo[kt][2] = packbf(bflo(sc[j1][0]), bflo(sc[j1][1]));
        plo[kt][3] = packbf(bflo(sc[j1][2]), bflo(sc[j1][3]));
    }

    // ---- ctx = P @ V  (K dim = keys, bounded by ktmax) ----
    float o4[8][4] = {};
    for (int kt = 0; kt < ktmax; kt++) {
        uint32_t ko = (uint32_t)(kt * 32);
        #pragma unroll
        for (int jp = 0; jp < 4; jp++) {
            uint32_t bh[4], bl[4];
            ldsm4(vBH + jp * 2304 + ko, bh[0], bh[1], bh[2], bh[3]);
            ldsm4(vBL + jp * 2304 + ko, bl[0], bl[1], bl[2], bl[3]);
            mma_bf16(o4[2*jp],   phi[kt][0], phi[kt][1], phi[kt][2], phi[kt][3], bh[0], bh[1]);
            mma_bf16(o4[2*jp],   phi[kt][0], phi[kt][1], phi[kt][2], phi[kt][3], bl[0], bl[1]);
            mma_bf16(o4[2*jp],   plo[kt][0], plo[kt][1], plo[kt][2], plo[kt][3], bh[0], bh[1]);
            mma_bf16(o4[2*jp+1], phi[kt][0], phi[kt][1], phi[kt][2], phi[kt][3], bh[2], bh[3]);
            mma_bf16(o4[2*jp+1], phi[kt][0], phi[kt][1], phi[kt][2], phi[kt][3], bl[2], bl[3]);
            mma_bf16(o4[2*jp+1], plo[kt][0], plo[kt][1], plo[kt][2], plo[kt][3], bh[2], bh[3]);
        }
    }

    // ---- scatter-add into g_ctx with query mask ----
    int rowA = r0 + g, rowB = r0 + g + 8;
    float qmA = qmv[rowA], qmB = qmv[rowB];
    float* baseA = g_ctx + ((size_t)src * SS + rowA) * DD + h * HDIM;
    float* baseB = g_ctx + ((size_t)src * SS + rowB) * DD + h * HDIM;
    #pragma unroll
    for (int jn = 0; jn < 8; jn++) {
        int col = jn * 8 + tg * 2;
        if (qmA > 0.f) {
            atomicAdd(baseA + col,     o4[jn][0] * qmA);
            atomicAdd(baseA + col + 1, o4[jn][1] * qmA);
        }
        if (qmB > 0.f) {
            atomicAdd(baseB + col,     o4[jn][2] * qmB);
            atomicAdd(baseB + col + 1, o4[jn][3] * qmB);
        }
    }
}

extern "C" void kernel_launch(void* const* d_in, const int* in_sizes, int n_in,
                              void* d_out, int out_size) {
    const float* nf    = (const float*)d_in[0];
    const float* masks = (const float*)d_in[1];
    const float* lnw   = (const float*)d_in[2];
    const float* lnb   = (const float*)d_in[3];
    const float* wq    = (const float*)d_in[4];
    const float* bq    = (const float*)d_in[5];
    const float* wk    = (const float*)d_in[6];
    const float* bk    = (const float*)d_in[7];
    const float* wv    = (const float*)d_in[8];
    const float* bv    = (const float*)d_in[9];
    const float* wo    = (const float*)d_in[10];
    const float* bo    = (const float*)d_in[11];
    const float* etw   = (const float*)d_in[12];
    const long long* ei = (const long long*)d_in[13];
    const long long* et = (const long long*)d_in[14];
    float* out = (float*)d_out;

    cudaFuncSetAttribute(qkv_mma_kernel, cudaFuncAttributeMaxDynamicSharedMemorySize, G_SMEM);
    cudaFuncSetAttribute(out_mma_kernel, cudaFuncAttributeMaxDynamicSharedMemorySize, G_SMEM);
    cudaFuncSetAttribute(attn_mma_kernel, cudaFuncAttributeMaxDynamicSharedMemorySize, A_SMEM);

    zero_ctx_kernel<<<4096, 256>>>();
    ln_kernel<<<ROWS / 8, 256>>>(nf, lnw, lnb);
    wconv_kernel<<<dim3(DD, 4), 256>>>(wq, wk, wv, wo);
    qkv_mma_kernel<<<dim3(ROWS / 128, DD / 128, 3), 256, G_SMEM>>>(bq, bk, bv);
    attn_mma_kernel<<<EE * HH, 128, A_SMEM>>>(ei, et, etw, masks);
    out_mma_kernel<<<dim3(ROWS / 128, DD / 128), 256, G_SMEM>>>(bo, nf, masks, out);
}

// round 5
// speedup vs baseline: 2.8572x; 1.0785x over previous
#include <cuda_runtime.h>
#include <cuda_bf16.h>
#include <math.h>
#include <stdint.h>

#define NN   1024
#define SS   64
#define DD   256
#define HH   4
#define HDIM 64
#define EE   4096
#define ROWS (NN*SS)   // 65536

// -------- scratch (allocation-free: device globals) --------
__device__ __nv_bfloat16 g_xn_hi[ROWS*DD];
__device__ __nv_bfloat16 g_xn_lo[ROWS*DD];
__device__ __nv_bfloat16 g_q_hi [ROWS*DD];   // pre-scaled by 1/8
__device__ __nv_bfloat16 g_q_lo [ROWS*DD];
__device__ __nv_bfloat16 g_k_hi [ROWS*DD];
__device__ __nv_bfloat16 g_k_lo [ROWS*DD];
__device__ __nv_bfloat16 g_v_hi [ROWS*DD];
__device__ __nv_bfloat16 g_v_lo [ROWS*DD];
__device__ float g_ctx[ROWS*DD];
__device__ __nv_bfloat16 g_wt_hi[4*DD*DD];   // transposed weights [n][k] (q,k,v,o)
__device__ __nv_bfloat16 g_wt_lo[4*DD*DD];

// ================= MMA / ldmatrix / cp.async helpers =================
__device__ __forceinline__ void mma_bf16(float c[4],
    uint32_t a0, uint32_t a1, uint32_t a2, uint32_t a3, uint32_t b0, uint32_t b1) {
    asm volatile(
        "mma.sync.aligned.m16n8k16.row.col.f32.bf16.bf16.f32 "
        "{%0,%1,%2,%3}, {%4,%5,%6,%7}, {%8,%9}, {%0,%1,%2,%3};"
        : "+f"(c[0]), "+f"(c[1]), "+f"(c[2]), "+f"(c[3])
        : "r"(a0), "r"(a1), "r"(a2), "r"(a3), "r"(b0), "r"(b1));
}
__device__ __forceinline__ void ldsm4(uint32_t a, uint32_t& r0, uint32_t& r1,
                                      uint32_t& r2, uint32_t& r3) {
    asm volatile("ldmatrix.sync.aligned.m8n8.x4.shared.b16 {%0,%1,%2,%3}, [%4];"
        : "=r"(r0), "=r"(r1), "=r"(r2), "=r"(r3) : "r"(a));
}
__device__ __forceinline__ void ldsm4t(uint32_t a, uint32_t& r0, uint32_t& r1,
                                       uint32_t& r2, uint32_t& r3) {
    asm volatile("ldmatrix.sync.aligned.m8n8.x4.trans.shared.b16 {%0,%1,%2,%3}, [%4];"
        : "=r"(r0), "=r"(r1), "=r"(r2), "=r"(r3) : "r"(a));
}
__device__ __forceinline__ void cpa16(uint32_t dst, const void* src) {
    asm volatile("cp.async.cg.shared.global [%0], [%1], 16;" :: "r"(dst), "l"(src));
}
__device__ __forceinline__ uint32_t smem_u32(const void* p) {
    uint32_t r;
    asm("{ .reg .u64 t; cvta.to.shared.u64 t, %1; cvt.u32.u64 %0, t; }" : "=r"(r) : "l"(p));
    return r;
}
__device__ __forceinline__ uint32_t packbf(float x, float y) {
    __nv_bfloat162 t = __floats2bfloat162_rn(x, y);
    return *(uint32_t*)&t;
}
__device__ __forceinline__ float bflo(float x) {
    return x - __bfloat162float(__float2bfloat16(x));
}
__device__ __forceinline__ void split4(float4 v, uint32_t& hi2a, uint32_t& hi2b,
                                       uint32_t& lo2a, uint32_t& lo2b) {
    hi2a = packbf(v.x, v.y); hi2b = packbf(v.z, v.w);
    lo2a = packbf(bflo(v.x), bflo(v.y)); lo2b = packbf(bflo(v.z), bflo(v.w));
}

// ---------------- zero the context accumulator ----------------
__global__ void zero_ctx_kernel() {
    size_t n4 = (size_t)ROWS * DD / 4;
    float4 z = make_float4(0.f, 0.f, 0.f, 0.f);
    for (size_t i = (size_t)blockIdx.x * blockDim.x + threadIdx.x; i < n4;
         i += (size_t)gridDim.x * blockDim.x)
        ((float4*)g_ctx)[i] = z;
}

// ---------------- LayerNorm -> bf16 hi/lo split ----------------
__global__ __launch_bounds__(256) void ln_kernel(
    const float* __restrict__ x, const float* __restrict__ w, const float* __restrict__ b) {
    int row  = blockIdx.x * 8 + (threadIdx.x >> 5);
    int lane = threadIdx.x & 31;
    const float4* xr = (const float4*)(x + (size_t)row * DD);
    float4 v0 = xr[lane];
    float4 v1 = xr[32 + lane];
    float s = v0.x + v0.y + v0.z + v0.w + v1.x + v1.y + v1.z + v1.w;
    #pragma unroll
    for (int o = 16; o; o >>= 1) s += __shfl_xor_sync(0xffffffffu, s, o);
    float mu = s * (1.0f / DD);
    float d0 = v0.x - mu, d1 = v0.y - mu, d2 = v0.z - mu, d3 = v0.w - mu;
    float d4 = v1.x - mu, d5 = v1.y - mu, d6 = v1.z - mu, d7 = v1.w - mu;
    float ss = d0*d0 + d1*d1 + d2*d2 + d3*d3 + d4*d4 + d5*d5 + d6*d6 + d7*d7;
    #pragma unroll
    for (int o = 16; o; o >>= 1) ss += __shfl_xor_sync(0xffffffffu, ss, o);
    float inv = rsqrtf(ss * (1.0f / DD) + 1e-5f);
    float4 w0 = ((const float4*)w)[lane], w1 = ((const float4*)w)[32 + lane];
    float4 b0 = ((const float4*)b)[lane], b1 = ((const float4*)b)[32 + lane];
    float4 o0 = make_float4(d0*inv*w0.x + b0.x, d1*inv*w0.y + b0.y,
                            d2*inv*w0.z + b0.z, d3*inv*w0.w + b0.w);
    float4 o1 = make_float4(d4*inv*w1.x + b1.x, d5*inv*w1.y + b1.y,
                            d6*inv*w1.z + b1.z, d7*inv*w1.w + b1.w);
    size_t base = (size_t)row * DD;
    uint32_t ha, hb, la, lb;
    split4(o0, ha, hb, la, lb);
    *(uint2*)(g_xn_hi + base + lane*4) = make_uint2(ha, hb);
    *(uint2*)(g_xn_lo + base + lane*4) = make_uint2(la, lb);
    split4(o1, ha, hb, la, lb);
    *(uint2*)(g_xn_hi + base + 128 + lane*4) = make_uint2(ha, hb);
    *(uint2*)(g_xn_lo + base + 128 + lane*4) = make_uint2(la, lb);
}

// ---------------- weight transpose + bf16 split ----------------
__global__ __launch_bounds__(256) void wconv_kernel(
    const float* __restrict__ wq, const float* __restrict__ wk,
    const float* __restrict__ wv, const float* __restrict__ wo) {
    int n = blockIdx.x, z = blockIdx.y, k = threadIdx.x;
    const float* w = (z == 0) ? wq : (z == 1) ? wk : (z == 2) ? wv : wo;
    float v = w[(size_t)k * DD + n];
    __nv_bfloat16 h = __float2bfloat16(v);
    __nv_bfloat16 l = __float2bfloat16(v - __bfloat162float(h));
    size_t o = (size_t)z * DD * DD + (size_t)n * DD + k;
    g_wt_hi[o] = h;
    g_wt_lo[o] = l;
}

// ================= pipelined QKV GEMM (cp.async 2-stage, k-chunk 32) =================
// per stage (stride-80B rows, 128 rows): AH(0) AL(10240) BH(20480) BL(30720); stage=40960
#define P_ST 40960
#define P_SMEM (2*P_ST)

__device__ __forceinline__ void qkv_load_chunk(
    uint32_t sbase, int tid, int kc,
    const __nv_bfloat16* aHi, const __nv_bfloat16* aLo, size_t m0,
    const __nv_bfloat16* bHi, const __nv_bfloat16* bLo, size_t n0) {
    #pragma unroll
    for (int it = 0; it < 2; it++) {
        int i = tid + it * 256;
        int row = i >> 2, seg = i & 3;
        uint32_t so = (uint32_t)(row * 80 + seg * 16);
        size_t ga = (size_t)(m0 + row) * DD + kc * 32 + seg * 8;
        size_t gb = (size_t)(n0 + row) * DD + kc * 32 + seg * 8;
        cpa16(sbase + so,         aHi + ga);
        cpa16(sbase + 10240 + so, aLo + ga);
        cpa16(sbase + 20480 + so, bHi + gb);
        cpa16(sbase + 30720 + so, bLo + gb);
    }
}

__global__ __launch_bounds__(256, 2) void qkv_mma_kernel(
    const float* __restrict__ bq, const float* __restrict__ bk, const float* __restrict__ bv) {
    extern __shared__ char sm[];
    uint32_t sbu = smem_u32(sm);
    int tid = threadIdx.x, lane = tid & 31, wid = tid >> 5;
    int g = lane >> 2, tg = lane & 3;
    int wm = wid & 3, wn = wid >> 2;
    int z = blockIdx.x >> 1;
    size_t n0 = (size_t)(blockIdx.x & 1) * 128;
    size_t m0 = (size_t)blockIdx.y * 128;
    const float* bias = (z == 0) ? bq : (z == 1) ? bk : bv;
    __nv_bfloat16* oh = (z == 0) ? g_q_hi : (z == 1) ? g_k_hi : g_v_hi;
    __nv_bfloat16* ol = (z == 0) ? g_q_lo : (z == 1) ? g_k_lo : g_v_lo;
    const __nv_bfloat16* Bh = g_wt_hi + (size_t)z * DD * DD;
    const __nv_bfloat16* Bl = g_wt_lo + (size_t)z * DD * DD;
    float scale = (z == 0) ? 0.125f : 1.0f;

    uint32_t aoff = (uint32_t)((lane & 15) * 80 + (lane >> 4) * 16) + (uint32_t)(wm * 32) * 80;
    uint32_t boff = (uint32_t)(((lane & 7) + ((lane >> 4) << 3)) * 80 + (lane & 8) * 2)
                    + (uint32_t)(wn * 64) * 80;

    float c[2][8][4] = {};

    qkv_load_chunk(sbu, tid, 0, g_xn_hi, g_xn_lo, m0, Bh, Bl, n0);
    asm volatile("cp.async.commit_group;" ::: "memory");

    for (int kc = 0; kc < 8; kc++) {
        int cur = kc & 1;
        if (kc < 7) {
            qkv_load_chunk(sbu + (cur ^ 1) * P_ST, tid, kc + 1, g_xn_hi, g_xn_lo, m0, Bh, Bl, n0);
            asm volatile("cp.async.commit_group;" ::: "memory");
            asm volatile("cp.async.wait_group 1;" ::: "memory");
        } else {
            asm volatile("cp.async.wait_group 0;" ::: "memory");
        }
        __syncthreads();

        uint32_t sA = sbu + cur * P_ST + aoff;
        uint32_t sB = sbu + cur * P_ST + 20480 + boff;
        #pragma unroll
        for (int kt = 0; kt < 2; kt++) {
            uint32_t ko = (uint32_t)(kt * 32);
            uint32_t ah[2][4], al[2][4];
            ldsm4(sA + ko,                ah[0][0], ah[0][1], ah[0][2], ah[0][3]);
            ldsm4(sA + 16 * 80 + ko,      ah[1][0], ah[1][1], ah[1][2], ah[1][3]);
            ldsm4(sA + 10240 + ko,        al[0][0], al[0][1], al[0][2], al[0][3]);
            ldsm4(sA + 10240 + 16*80 + ko, al[1][0], al[1][1], al[1][2], al[1][3]);
            #pragma unroll
            for (int jp = 0; jp < 4; jp++) {
                uint32_t bh[4], bl[4];
                ldsm4(sB + jp * 1280 + ko,         bh[0], bh[1], bh[2], bh[3]);
                ldsm4(sB + 10240 + jp * 1280 + ko, bl[0], bl[1], bl[2], bl[3]);
                #pragma unroll
                for (int mi = 0; mi < 2; mi++) {
                    mma_bf16(c[mi][2*jp],   ah[mi][0], ah[mi][1], ah[mi][2], ah[mi][3], bh[0], bh[1]);
                    mma_bf16(c[mi][2*jp],   ah[mi][0], ah[mi][1], ah[mi][2], ah[mi][3], bl[0], bl[1]);
                    mma_bf16(c[mi][2*jp],   al[mi][0], al[mi][1], al[mi][2], al[mi][3], bh[0], bh[1]);
                    mma_bf16(c[mi][2*jp+1], ah[mi][0], ah[mi][1], ah[mi][2], ah[mi][3], bh[2], bh[3]);
                    mma_bf16(c[mi][2*jp+1], ah[mi][0], ah[mi][1], ah[mi][2], ah[mi][3], bl[2], bl[3]);
                    mma_bf16(c[mi][2*jp+1], al[mi][0], al[mi][1], al[mi][2], al[mi][3], bh[2], bh[3]);
                }
            }
        }
        __syncthreads();
    }

    #pragma unroll
    for (int mi = 0; mi < 2; mi++) {
        int rA = (int)m0 + wm * 32 + mi * 16 + g;
        int rB = rA + 8;
        #pragma unroll
        for (int ni = 0; ni < 8; ni++) {
            int n = (int)n0 + wn * 64 + ni * 8 + tg * 2;
            float b0v = bias[n], b1v = bias[n + 1];
            float v0 = (c[mi][ni][0] + b0v) * scale;
            float v1 = (c[mi][ni][1] + b1v) * scale;
            float v2 = (c[mi][ni][2] + b0v) * scale;
            float v3 = (c[mi][ni][3] + b1v) * scale;
            *(uint32_t*)(oh + (size_t)rA * DD + n) = packbf(v0, v1);
            *(uint32_t*)(ol + (size_t)rA * DD + n) = packbf(bflo(v0), bflo(v1));
            *(uint32_t*)(oh + (size_t)rB * DD + n) = packbf(v2, v3);
            *(uint32_t*)(ol + (size_t)rB * DD + n) = packbf(bflo(v2), bflo(v3));
        }
    }
}

// ================= out GEMM (fp32-A fused split, unpipelined) =================
#define G_AHI 0
#define G_ALO 18432
#define G_BHI 36864
#define G_BLO 55296
#define G_SMEM 73728

__global__ __launch_bounds__(256, 2) void out_mma_kernel(
    const float* __restrict__ bo, const float* __restrict__ nf,
    const float* __restrict__ masks, float* __restrict__ out) {
    extern __shared__ char sm[];
    uint32_t sbu = smem_u32(sm);
    int tid = threadIdx.x, lane = tid & 31, wid = tid >> 5;
    int g = lane >> 2, tg = lane & 3;
    int wm = wid & 3, wn = wid >> 2;
    size_t m0 = (size_t)blockIdx.x * 128, n0 = (size_t)blockIdx.y * 128;
    const __nv_bfloat16* Bh = g_wt_hi + (size_t)3 * DD * DD;
    const __nv_bfloat16* Bl = g_wt_lo + (size_t)3 * DD * DD;

    uint32_t aoff = (uint32_t)(((lane & 15) * 72 + (lane >> 4) * 8) * 2);
    uint32_t boff = (uint32_t)((((lane & 7) + ((lane >> 4) << 3)) * 72 + (lane & 8)) * 2);
    uint32_t aB0 = sbu + G_AHI + aoff + (uint32_t)(wm * 32) * 144;
    uint32_t aB1 = aB0 + 16 * 144;
    uint32_t bB  = sbu + G_BHI + boff + (uint32_t)(wn * 64) * 144;

    float c[2][8][4] = {};
    for (int kc = 0; kc < 4; kc++) {
        __syncthreads();
        #pragma unroll
        for (int it = 0; it < 4; it++) {
            int i = tid + it * 256;
            int row = i >> 3, seg = i & 7;
            int so = (row * 72 + seg * 8) * 2;
            size_t ga = (size_t)(m0 + row) * DD + kc * 64 + seg * 8;
            size_t gb = (size_t)(n0 + row) * DD + kc * 64 + seg * 8;
            float4 f0 = *(const float4*)(g_ctx + ga);
            float4 f1 = *(const float4*)(g_ctx + ga + 4);
            uint32_t ha, hb, la, lb, hc, hd, lc, ld;
            split4(f0, ha, hb, la, lb);
            split4(f1, hc, hd, lc, ld);
            *(uint4*)(sm + G_AHI + so) = make_uint4(ha, hb, hc, hd);
            *(uint4*)(sm + G_ALO + so) = make_uint4(la, lb, lc, ld);
            *(uint4*)(sm + G_BHI + so) = *(const uint4*)(Bh + gb);
            *(uint4*)(sm + G_BLO + so) = *(const uint4*)(Bl + gb);
        }
        __syncthreads();
        #pragma unroll
        for (int kt = 0; kt < 4; kt++) {
            uint32_t ko = (uint32_t)(kt * 32);
            uint32_t ah[2][4], al[2][4];
            ldsm4(aB0 + ko,                     ah[0][0], ah[0][1], ah[0][2], ah[0][3]);
            ldsm4(aB1 + ko,                     ah[1][0], ah[1][1], ah[1][2], ah[1][3]);
            ldsm4(aB0 + (G_ALO - G_AHI) + ko,   al[0][0], al[0][1], al[0][2], al[0][3]);
            ldsm4(aB1 + (G_ALO - G_AHI) + ko,   al[1][0], al[1][1], al[1][2], al[1][3]);
            #pragma unroll
            for (int jp = 0; jp < 4; jp++) {
                uint32_t bh[4], bl[4];
                ldsm4(bB + jp * 2304 + ko,                   bh[0], bh[1], bh[2], bh[3]);
                ldsm4(bB + (G_BLO - G_BHI) + jp * 2304 + ko, bl[0], bl[1], bl[2], bl[3]);
                #pragma unroll
                for (int mi = 0; mi < 2; mi++) {
                    mma_bf16(c[mi][2*jp],   ah[mi][0], ah[mi][1], ah[mi][2], ah[mi][3], bh[0], bh[1]);
                    mma_bf16(c[mi][2*jp],   ah[mi][0], ah[mi][1], ah[mi][2], ah[mi][3], bl[0], bl[1]);
                    mma_bf16(c[mi][2*jp],   al[mi][0], al[mi][1], al[mi][2], al[mi][3], bh[0], bh[1]);
                    mma_bf16(c[mi][2*jp+1], ah[mi][0], ah[mi][1], ah[mi][2], ah[mi][3], bh[2], bh[3]);
                    mma_bf16(c[mi][2*jp+1], ah[mi][0], ah[mi][1], ah[mi][2], ah[mi][3], bl[2], bl[3]);
                    mma_bf16(c[mi][2*jp+1], al[mi][0], al[mi][1], al[mi][2], al[mi][3], bh[2], bh[3]);
                }
            }
        }
    }

    #pragma unroll
    for (int mi = 0; mi < 2; mi++) {
        int rA = (int)m0 + wm * 32 + mi * 16 + g;
        int rB = rA + 8;
        float mkA = masks[rA], mkB = masks[rB];
        #pragma unroll
        for (int ni = 0; ni < 8; ni++) {
            int n = (int)n0 + wn * 64 + ni * 8 + tg * 2;
            float b0v = bo[n], b1v = bo[n + 1];
            float2 resA = *(const float2*)(nf + (size_t)rA * DD + n);
            float2 resB = *(const float2*)(nf + (size_t)rB * DD + n);
            float2 oA = make_float2((c[mi][ni][0] + b0v + resA.x) * mkA,
                                    (c[mi][ni][1] + b1v + resA.y) * mkA);
            float2 oB = make_float2((c[mi][ni][2] + b0v + resB.x) * mkB,
                                    (c[mi][ni][3] + b1v + resB.y) * mkB);
            *(float2*)(out + (size_t)rA * DD + n) = oA;
            *(float2*)(out + (size_t)rB * DD + n) = oB;
        }
    }
}

// ---------------- per-(edge, head) attention: HMMA + ldmatrix(.trans V) + mask skipping ----------------
#define A_QH 0
#define A_QL 9216
#define A_KH 18432
#define A_KL 27648
#define A_VH 36864
#define A_VL 46080
#define A_KM 55296
#define A_QM 55552
#define A_SMEM 55808

__global__ __launch_bounds__(128, 4) void attn_mma_kernel(
    const long long* __restrict__ ei, const long long* __restrict__ et,
    const float* __restrict__ etw, const float* __restrict__ masks) {
    extern __shared__ char sm[];
    uint32_t sbu = smem_u32(sm);
    float* kmv = (float*)(sm + A_KM);
    float* qmv = (float*)(sm + A_QM);

    int e = blockIdx.x >> 2;
    int h = blockIdx.x & 3;
    int tid = threadIdx.x, lane = tid & 31, wid = tid >> 5;
    int g = lane >> 2, tg = lane & 3;

    bool is64 = true;
    #pragma unroll
    for (int i = 0; i < 16; i++) {
        long long v = ei[i];
        if (v < 0 || v >= NN) { is64 = false; break; }
    }
    const int* ei32 = (const int*)ei;
    const int* et32 = (const int*)et;
    int src = is64 ? (int)ei[e]      : ei32[e];
    int dst = is64 ? (int)ei[EE + e] : ei32[EE + e];
    int tt  = is64 ? (int)et[e]      : et32[e];
    float xw = etw[tt - 1];
    float sp = (xw > 20.f) ? xw : log1pf(__expf(xw));
    float ew = fminf(fmaxf(sp, 1e-6f), 1e6f);

    float md0 = masks[(size_t)dst * SS + lane], md1 = masks[(size_t)dst * SS + 32 + lane];
    float ms0 = masks[(size_t)src * SS + lane], ms1 = masks[(size_t)src * SS + 32 + lane];
    int len_dst = __popc(__ballot_sync(0xffffffffu, md0 > 0.f)) +
                  __popc(__ballot_sync(0xffffffffu, md1 > 0.f));
    int len_src = __popc(__ballot_sync(0xffffffffu, ms0 > 0.f)) +
                  __popc(__ballot_sync(0xffffffffu, ms1 > 0.f));
    int lq = (len_src + 15) & ~15;
    int lk = (len_dst + 15) & ~15;
    int jpmax = (((len_dst + 7) >> 3) + 1) >> 1;
    int ktmax = (len_dst + 15) >> 4;

    // ---- stage q/k/v row-major hi/lo tiles ----
    size_t qbase = ((size_t)src * SS) * DD + h * HDIM;
    size_t kbase = ((size_t)dst * SS) * DD + h * HDIM;
    for (int i = tid; i < 512; i += 128) {
        int row = i >> 3, seg = i & 7;
        int so = (row * 72 + seg * 8) * 2;
        size_t go = (size_t)row * DD + seg * 8;
        if (row < lq) {
            *(uint4*)(sm + A_QH + so) = *(const uint4*)(g_q_hi + qbase + go);
            *(uint4*)(sm + A_QL + so) = *(const uint4*)(g_q_lo + qbase + go);
        }
        if (row < lk) {
            *(uint4*)(sm + A_KH + so) = *(const uint4*)(g_k_hi + kbase + go);
            *(uint4*)(sm + A_KL + so) = *(const uint4*)(g_k_lo + kbase + go);
            *(uint4*)(sm + A_VH + so) = *(const uint4*)(g_v_hi + kbase + go);
            *(uint4*)(sm + A_VL + so) = *(const uint4*)(g_v_lo + kbase + go);
        }
    }
    if (tid < 32) { kmv[lane] = md0; kmv[32 + lane] = md1; }
    else if (tid < 64) { qmv[lane] = ms0; qmv[32 + lane] = ms1; }
    __syncthreads();

    int r0 = wid * 16;
    if (r0 >= len_src) return;   // whole-warp skip; no further block syncs

    uint32_t aoff = (uint32_t)(((lane & 15) * 72 + (lane >> 4) * 8) * 2);
    uint32_t boff = (uint32_t)((((lane & 7) + ((lane >> 4) << 3)) * 72 + (lane & 8)) * 2);
    uint32_t voff = (uint32_t)((lane & 15) * 144 + (lane >> 4) * 16);
    uint32_t qBH = sbu + A_QH + aoff + (uint32_t)r0 * 144;
    uint32_t qBL = qBH + (A_QL - A_QH);
    uint32_t kBH = sbu + A_KH + boff;
    uint32_t kBL = kBH + (A_KL - A_KH);
    uint32_t vBH = sbu + A_VH + voff;
    uint32_t vBL = vBH + (A_VL - A_VH);

    // ---- scores = (q/8) @ k^T ----
    float sc[8][4] = {};
    #pragma unroll
    for (int kt = 0; kt < 4; kt++) {
        uint32_t ko = (uint32_t)(kt * 32);
        uint32_t ah[4], al[4];
        ldsm4(qBH + ko, ah[0], ah[1], ah[2], ah[3]);
        ldsm4(qBL + ko, al[0], al[1], al[2], al[3]);
        for (int jp = 0; jp < jpmax; jp++) {
            uint32_t bh[4], bl[4];
            ldsm4(kBH + jp * 2304 + ko, bh[0], bh[1], bh[2], bh[3]);
            ldsm4(kBL + jp * 2304 + ko, bl[0], bl[1], bl[2], bl[3]);
            mma_bf16(sc[2*jp],   ah[0], ah[1], ah[2], ah[3], bh[0], bh[1]);
            mma_bf16(sc[2*jp],   ah[0], ah[1], ah[2], ah[3], bl[0], bl[1]);
            mma_bf16(sc[2*jp],   al[0], al[1], al[2], al[3], bh[0], bh[1]);
            mma_bf16(sc[2*jp+1], ah[0], ah[1], ah[2], ah[3], bh[2], bh[3]);
            mma_bf16(sc[2*jp+1], ah[0], ah[1], ah[2], ah[3], bl[2], bl[3]);
            mma_bf16(sc[2*jp+1], al[0], al[1], al[2], al[3], bh[2], bh[3]);
        }
    }

    // ---- bias + key mask + softmax ----
    float kmr[8][2];
    #pragma unroll
    for (int jn = 0; jn < 8; jn++) {
        int col = jn * 8 + tg * 2;
        kmr[jn][0] = kmv[col];
        kmr[jn][1] = kmv[col + 1];
        sc[jn][0] = (kmr[jn][0] > 0.f) ? sc[jn][0] + ew : -1e30f;
        sc[jn][1] = (kmr[jn][1] > 0.f) ? sc[jn][1] + ew : -1e30f;
        sc[jn][2] = (kmr[jn][0] > 0.f) ? sc[jn][2] + ew : -1e30f;
        sc[jn][3] = (kmr[jn][1] > 0.f) ? sc[jn][3] + ew : -1e30f;
    }
    float mA = -1e30f, mB = -1e30f;
    #pragma unroll
    for (int jn = 0; jn < 8; jn++) {
        mA = fmaxf(mA, fmaxf(sc[jn][0], sc[jn][1]));
        mB = fmaxf(mB, fmaxf(sc[jn][2], sc[jn][3]));
    }
    mA = fmaxf(mA, __shfl_xor_sync(0xffffffffu, mA, 1));
    mA = fmaxf(mA, __shfl_xor_sync(0xffffffffu, mA, 2));
    mB = fmaxf(mB, __shfl_xor_sync(0xffffffffu, mB, 1));
    mB = fmaxf(mB, __shfl_xor_sync(0xffffffffu, mB, 2));
    float sA = 0.f, sB = 0.f;
    #pragma unroll
    for (int jn = 0; jn < 8; jn++) {
        sc[jn][0] = __expf(sc[jn][0] - mA); sA += sc[jn][0];
        sc[jn][1] = __expf(sc[jn][1] - mA); sA += sc[jn][1];
        sc[jn][2] = __expf(sc[jn][2] - mB); sB += sc[jn][2];
        sc[jn][3] = __expf(sc[jn][3] - mB); sB += sc[jn][3];
    }
    sA += __shfl_xor_sync(0xffffffffu, sA, 1);
    sA += __shfl_xor_sync(0xffffffffu, sA, 2);
    sB += __shfl_xor_sync(0xffffffffu, sB, 1);
    sB += __shfl_xor_sync(0xffffffffu, sB, 2);
    float iA = 1.0f / sA, iB = 1.0f / sB;
    #pragma unroll
    for (int jn = 0; jn < 8; jn++) {
        sc[jn][0] *= iA * kmr[jn][0];
        sc[jn][1] *= iA * kmr[jn][1];
        sc[jn][2] *= iB * kmr[jn][0];
        sc[jn][3] *= iB * kmr[jn][1];
    }

    // ---- repack P (C-frag -> A-frag), hi/lo ----
    uint32_t phi[4][4], plo[4][4];
    #pragma unroll
    for (int kt = 0; kt < 4; kt++) {
        int j0 = 2 * kt, j1 = 2 * kt + 1;
        phi[kt][0] = packbf(sc[j0][0], sc[j0][1]);
        phi[kt][1] = packbf(sc[j0][2], sc[j0][3]);
        phi[kt][2] = packbf(sc[j1][0], sc[j1][1]);
        phi[kt][3] = packbf(sc[j1][2], sc[j1][3]);
        plo[kt][0] = packbf(bflo(sc[j0][0]), bflo(sc[j0][1]));
        plo[kt][1] = packbf(bflo(sc[j0][2]), bflo(sc[j0][3]));
        plo[kt][2] = packbf(bflo(sc[j1][0]), bflo(sc[j1][1]));
        plo[kt][3] = packbf(bflo(sc[j1][2]), bflo(sc[j1][3]));
    }

    // ---- ctx = P @ V via ldmatrix.trans on row-major V ----
    float o4[8][4] = {};
    for (int kt = 0; kt < ktmax; kt++) {
        uint32_t ko = (uint32_t)(kt * 2304);  // 16 key rows * 144B
        #pragma unroll
        for (int jp = 0; jp < 4; jp++) {
            uint32_t bh[4], bl[4];
            ldsm4t(vBH + ko + jp * 32, bh[0], bh[1], bh[2], bh[3]);
            ldsm4t(vBL + ko + jp * 32, bl[0], bl[1], bl[2], bl[3]);
            mma_bf16(o4[2*jp],   phi[kt][0], phi[kt][1], phi[kt][2], phi[kt][3], bh[0], bh[1]);
            mma_bf16(o4[2*jp],   phi[kt][0], phi[kt][1], phi[kt][2], phi[kt][3], bl[0], bl[1]);
            mma_bf16(o4[2*jp],   plo[kt][0], plo[kt][1], plo[kt][2], plo[kt][3], bh[0], bh[1]);
            mma_bf16(o4[2*jp+1], phi[kt][0], phi[kt][1], phi[kt][2], phi[kt][3], bh[2], bh[3]);
            mma_bf16(o4[2*jp+1], phi[kt][0], phi[kt][1], phi[kt][2], phi[kt][3], bl[2], bl[3]);
            mma_bf16(o4[2*jp+1], plo[kt][0], plo[kt][1], plo[kt][2], plo[kt][3], bh[2], bh[3]);
        }
    }

    // ---- scatter-add into g_ctx with query mask ----
    int rowA = r0 + g, rowB = r0 + g + 8;
    float qmA = qmv[rowA], qmB = qmv[rowB];
    float* baseA = g_ctx + ((size_t)src * SS + rowA) * DD + h * HDIM;
    float* baseB = g_ctx + ((size_t)src * SS + rowB) * DD + h * HDIM;
    #pragma unroll
    for (int jn = 0; jn < 8; jn++) {
        int col = jn * 8 + tg * 2;
        if (qmA > 0.f) {
            atomicAdd(baseA + col,     o4[jn][0] * qmA);
            atomicAdd(baseA + col + 1, o4[jn][1] * qmA);
        }
        if (qmB > 0.f) {
            atomicAdd(baseB + col,     o4[jn][2] * qmB);
            atomicAdd(baseB + col + 1, o4[jn][3] * qmB);
        }
    }
}

extern "C" void kernel_launch(void* const* d_in, const int* in_sizes, int n_in,
                              void* d_out, int out_size) {
    const float* nf    = (const float*)d_in[0];
    const float* masks = (const float*)d_in[1];
    const float* lnw   = (const float*)d_in[2];
    const float* lnb   = (const float*)d_in[3];
    const float* wq    = (const float*)d_in[4];
    const float* bq    = (const float*)d_in[5];
    const float* wk    = (const float*)d_in[6];
    const float* bk    = (const float*)d_in[7];
    const float* wv    = (const float*)d_in[8];
    const float* bv    = (const float*)d_in[9];
    const float* wo    = (const float*)d_in[10];
    const float* bo    = (const float*)d_in[11];
    const float* etw   = (const float*)d_in[12];
    const long long* ei = (const long long*)d_in[13];
    const long long* et = (const long long*)d_in[14];
    float* out = (float*)d_out;

    cudaFuncSetAttribute(qkv_mma_kernel, cudaFuncAttributeMaxDynamicSharedMemorySize, P_SMEM);
    cudaFuncSetAttribute(out_mma_kernel, cudaFuncAttributeMaxDynamicSharedMemorySize, G_SMEM);
    cudaFuncSetAttribute(attn_mma_kernel, cudaFuncAttributeMaxDynamicSharedMemorySize, A_SMEM);

    zero_ctx_kernel<<<4096, 256>>>();
    ln_kernel<<<ROWS / 8, 256>>>(nf, lnw, lnb);
    wconv_kernel<<<dim3(DD, 4), 256>>>(wq, wk, wv, wo);
    qkv_mma_kernel<<<dim3(6, ROWS / 128), 256, P_SMEM>>>(bq, bk, bv);
    attn_mma_kernel<<<EE * HH, 128, A_SMEM>>>(ei, et, etw, masks);
    out_mma_kernel<<<dim3(ROWS / 128, DD / 128), 256, G_SMEM>>>(bo, nf, masks, out);
}

// round 6
// speedup vs baseline: 3.0443x; 1.0655x over previous
#include <cuda_runtime.h>
#include <cuda_bf16.h>
#include <math.h>
#include <stdint.h>

#define NN   1024
#define SS   64
#define DD   256
#define HH   4
#define HDIM 64
#define EE   4096
#define ROWS (NN*SS)   // 65536

// -------- scratch (allocation-free: device globals) --------
__device__ __nv_bfloat16 g_xn_hi[ROWS*DD];
__device__ __nv_bfloat16 g_xn_lo[ROWS*DD];
__device__ __nv_bfloat16 g_q_hi [ROWS*DD];   // pre-scaled by 1/8
__device__ __nv_bfloat16 g_q_lo [ROWS*DD];
__device__ __nv_bfloat16 g_k_hi [ROWS*DD];
__device__ __nv_bfloat16 g_k_lo [ROWS*DD];
__device__ __nv_bfloat16 g_v_hi [ROWS*DD];
__device__ __nv_bfloat16 g_v_lo [ROWS*DD];
__device__ float g_ctx[ROWS*DD];
__device__ __nv_bfloat16 g_wt_hi[4*DD*DD];   // transposed weights [n][k] (q,k,v,o)
__device__ __nv_bfloat16 g_wt_lo[4*DD*DD];

// ================= MMA / ldmatrix helpers =================
__device__ __forceinline__ void mma_bf16(float c[4],
    uint32_t a0, uint32_t a1, uint32_t a2, uint32_t a3, uint32_t b0, uint32_t b1) {
    asm volatile(
        "mma.sync.aligned.m16n8k16.row.col.f32.bf16.bf16.f32 "
        "{%0,%1,%2,%3}, {%4,%5,%6,%7}, {%8,%9}, {%0,%1,%2,%3};"
        : "+f"(c[0]), "+f"(c[1]), "+f"(c[2]), "+f"(c[3])
        : "r"(a0), "r"(a1), "r"(a2), "r"(a3), "r"(b0), "r"(b1));
}
__device__ __forceinline__ void ldsm4(uint32_t a, uint32_t& r0, uint32_t& r1,
                                      uint32_t& r2, uint32_t& r3) {
    asm volatile("ldmatrix.sync.aligned.m8n8.x4.shared.b16 {%0,%1,%2,%3}, [%4];"
        : "=r"(r0), "=r"(r1), "=r"(r2), "=r"(r3) : "r"(a));
}
__device__ __forceinline__ void ldsm4t(uint32_t a, uint32_t& r0, uint32_t& r1,
                                       uint32_t& r2, uint32_t& r3) {
    asm volatile("ldmatrix.sync.aligned.m8n8.x4.trans.shared.b16 {%0,%1,%2,%3}, [%4];"
        : "=r"(r0), "=r"(r1), "=r"(r2), "=r"(r3) : "r"(a));
}
__device__ __forceinline__ uint32_t smem_u32(const void* p) {
    uint32_t r;
    asm("{ .reg .u64 t; cvta.to.shared.u64 t, %1; cvt.u32.u64 %0, t; }" : "=r"(r) : "l"(p));
    return r;
}
__device__ __forceinline__ uint32_t packbf(float x, float y) {
    __nv_bfloat162 t = __floats2bfloat162_rn(x, y);
    return *(uint32_t*)&t;
}
__device__ __forceinline__ float bflo(float x) {
    return x - __bfloat162float(__float2bfloat16(x));
}
__device__ __forceinline__ void split4(float4 v, uint32_t& hi2a, uint32_t& hi2b,
                                       uint32_t& lo2a, uint32_t& lo2b) {
    hi2a = packbf(v.x, v.y); hi2b = packbf(v.z, v.w);
    lo2a = packbf(bflo(v.x), bflo(v.y)); lo2b = packbf(bflo(v.z), bflo(v.w));
}

// ---------------- zero the context accumulator ----------------
__global__ void zero_ctx_kernel() {
    size_t n4 = (size_t)ROWS * DD / 4;
    float4 z = make_float4(0.f, 0.f, 0.f, 0.f);
    for (size_t i = (size_t)blockIdx.x * blockDim.x + threadIdx.x; i < n4;
         i += (size_t)gridDim.x * blockDim.x)
        ((float4*)g_ctx)[i] = z;
}

// ---------------- LayerNorm -> bf16 hi/lo split (mask-skipped) ----------------
__global__ __launch_bounds__(256) void ln_kernel(
    const float* __restrict__ x, const float* __restrict__ w, const float* __restrict__ b,
    const float* __restrict__ masks) {
    int row  = blockIdx.x * 8 + (threadIdx.x >> 5);
    int lane = threadIdx.x & 31;
    if (masks[row & ~15] <= 0.f) return;   // 16-row frag never consumed downstream
    const float4* xr = (const float4*)(x + (size_t)row * DD);
    float4 v0 = xr[lane];
    float4 v1 = xr[32 + lane];
    float s = v0.x + v0.y + v0.z + v0.w + v1.x + v1.y + v1.z + v1.w;
    #pragma unroll
    for (int o = 16; o; o >>= 1) s += __shfl_xor_sync(0xffffffffu, s, o);
    float mu = s * (1.0f / DD);
    float d0 = v0.x - mu, d1 = v0.y - mu, d2 = v0.z - mu, d3 = v0.w - mu;
    float d4 = v1.x - mu, d5 = v1.y - mu, d6 = v1.z - mu, d7 = v1.w - mu;
    float ss = d0*d0 + d1*d1 + d2*d2 + d3*d3 + d4*d4 + d5*d5 + d6*d6 + d7*d7;
    #pragma unroll
    for (int o = 16; o; o >>= 1) ss += __shfl_xor_sync(0xffffffffu, ss, o);
    float inv = rsqrtf(ss * (1.0f / DD) + 1e-5f);
    float4 w0 = ((const float4*)w)[lane], w1 = ((const float4*)w)[32 + lane];
    float4 b0 = ((const float4*)b)[lane], b1 = ((const float4*)b)[32 + lane];
    float4 o0 = make_float4(d0*inv*w0.x + b0.x, d1*inv*w0.y + b0.y,
                            d2*inv*w0.z + b0.z, d3*inv*w0.w + b0.w);
    float4 o1 = make_float4(d4*inv*w1.x + b1.x, d5*inv*w1.y + b1.y,
                            d6*inv*w1.z + b1.z, d7*inv*w1.w + b1.w);
    size_t base = (size_t)row * DD;
    uint32_t ha, hb, la, lb;
    split4(o0, ha, hb, la, lb);
    *(uint2*)(g_xn_hi + base + lane*4) = make_uint2(ha, hb);
    *(uint2*)(g_xn_lo + base + lane*4) = make_uint2(la, lb);
    split4(o1, ha, hb, la, lb);
    *(uint2*)(g_xn_hi + base + 128 + lane*4) = make_uint2(ha, hb);
    *(uint2*)(g_xn_lo + base + 128 + lane*4) = make_uint2(la, lb);
}

// ---------------- weight transpose + bf16 split ----------------
__global__ __launch_bounds__(256) void wconv_kernel(
    const float* __restrict__ wq, const float* __restrict__ wk,
    const float* __restrict__ wv, const float* __restrict__ wo) {
    int n = blockIdx.x, z = blockIdx.y, k = threadIdx.x;
    const float* w = (z == 0) ? wq : (z == 1) ? wk : (z == 2) ? wv : wo;
    float v = w[(size_t)k * DD + n];
    __nv_bfloat16 h = __float2bfloat16(v);
    __nv_bfloat16 l = __float2bfloat16(v - __bfloat162float(h));
    size_t o = (size_t)z * DD * DD + (size_t)n * DD + k;
    g_wt_hi[o] = h;
    g_wt_lo[o] = l;
}

// ================= HMMA GEMM smem layout =================
#define G_AHI 0
#define G_ALO 18432
#define G_BHI 36864
#define G_BLO 55296
#define G_SMEM 73728

// ---------------- QKV projection (HMMA, mask-skipped) ----------------
// grid (6, 512): x = z*2 + n-half (L2 reuse of A across the 6 same-m blocks)
__global__ __launch_bounds__(256, 2) void qkv_mma_kernel(
    const float* __restrict__ bq, const float* __restrict__ bk, const float* __restrict__ bv,
    const float* __restrict__ masks) {
    extern __shared__ char sm[];
    uint32_t sbu = smem_u32(sm);
    int tid = threadIdx.x, lane = tid & 31, wid = tid >> 5;
    int g = lane >> 2, tg = lane & 3;
    int wm = wid & 3, wn = wid >> 2;
    int z = blockIdx.x >> 1;
    size_t n0 = (size_t)(blockIdx.x & 1) * 128;
    size_t m0 = (size_t)blockIdx.y * 128;
    const float* bias = (z == 0) ? bq : (z == 1) ? bk : bv;
    __nv_bfloat16* oh = (z == 0) ? g_q_hi : (z == 1) ? g_k_hi : g_v_hi;
    __nv_bfloat16* ol = (z == 0) ? g_q_lo : (z == 1) ? g_k_lo : g_v_lo;
    const __nv_bfloat16* Bh = g_wt_hi + (size_t)z * DD * DD;
    const __nv_bfloat16* Bl = g_wt_lo + (size_t)z * DD * DD;
    float scale = (z == 0) ? 0.125f : 1.0f;

    bool act0 = masks[m0 + wm * 32] > 0.f;        // frag rows wm*32..+15
    bool act1 = masks[m0 + wm * 32 + 16] > 0.f;   // frag rows wm*32+16..+31

    uint32_t aoff = (uint32_t)(((lane & 15) * 72 + (lane >> 4) * 8) * 2);
    uint32_t boff = (uint32_t)((((lane & 7) + ((lane >> 4) << 3)) * 72 + (lane & 8)) * 2);
    uint32_t aB0 = sbu + G_AHI + aoff + (uint32_t)(wm * 32) * 144;
    uint32_t aB1 = aB0 + 16 * 144;
    uint32_t bB  = sbu + G_BHI + boff + (uint32_t)(wn * 64) * 144;

    float c[2][8][4] = {};
    for (int kc = 0; kc < 4; kc++) {
        __syncthreads();
        #pragma unroll
        for (int it = 0; it < 4; it++) {
            int i = tid + it * 256;
            int row = i >> 3, seg = i & 7;
            int so = (row * 72 + seg * 8) * 2;
            size_t gb = (size_t)(n0 + row) * DD + kc * 64 + seg * 8;
            if (masks[m0 + (row & ~15)] > 0.f) {
                size_t ga = (size_t)(m0 + row) * DD + kc * 64 + seg * 8;
                *(uint4*)(sm + G_AHI + so) = *(const uint4*)(g_xn_hi + ga);
                *(uint4*)(sm + G_ALO + so) = *(const uint4*)(g_xn_lo + ga);
            }
            *(uint4*)(sm + G_BHI + so) = *(const uint4*)(Bh + gb);
            *(uint4*)(sm + G_BLO + so) = *(const uint4*)(Bl + gb);
        }
        __syncthreads();
        if (act0 || act1) {
            #pragma unroll
            for (int kt = 0; kt < 4; kt++) {
                uint32_t ko = (uint32_t)(kt * 32);
                uint32_t ah[2][4], al[2][4];
                if (act0) {
                    ldsm4(aB0 + ko,                   ah[0][0], ah[0][1], ah[0][2], ah[0][3]);
                    ldsm4(aB0 + (G_ALO - G_AHI) + ko, al[0][0], al[0][1], al[0][2], al[0][3]);
                }
                if (act1) {
                    ldsm4(aB1 + ko,                   ah[1][0], ah[1][1], ah[1][2], ah[1][3]);
                    ldsm4(aB1 + (G_ALO - G_AHI) + ko, al[1][0], al[1][1], al[1][2], al[1][3]);
                }
                #pragma unroll
                for (int jp = 0; jp < 4; jp++) {
                    uint32_t bh[4], bl[4];
                    ldsm4(bB + jp * 2304 + ko,                   bh[0], bh[1], bh[2], bh[3]);
                    ldsm4(bB + (G_BLO - G_BHI) + jp * 2304 + ko, bl[0], bl[1], bl[2], bl[3]);
                    if (act0) {
                        mma_bf16(c[0][2*jp],   ah[0][0], ah[0][1], ah[0][2], ah[0][3], bh[0], bh[1]);
                        mma_bf16(c[0][2*jp],   ah[0][0], ah[0][1], ah[0][2], ah[0][3], bl[0], bl[1]);
                        mma_bf16(c[0][2*jp],   al[0][0], al[0][1], al[0][2], al[0][3], bh[0], bh[1]);
                        mma_bf16(c[0][2*jp+1], ah[0][0], ah[0][1], ah[0][2], ah[0][3], bh[2], bh[3]);
                        mma_bf16(c[0][2*jp+1], ah[0][0], ah[0][1], ah[0][2], ah[0][3], bl[2], bl[3]);
                        mma_bf16(c[0][2*jp+1], al[0][0], al[0][1], al[0][2], al[0][3], bh[2], bh[3]);
                    }
                    if (act1) {
                        mma_bf16(c[1][2*jp],   ah[1][0], ah[1][1], ah[1][2], ah[1][3], bh[0], bh[1]);
                        mma_bf16(c[1][2*jp],   ah[1][0], ah[1][1], ah[1][2], ah[1][3], bl[0], bl[1]);
                        mma_bf16(c[1][2*jp],   al[1][0], al[1][1], al[1][2], al[1][3], bh[0], bh[1]);
                        mma_bf16(c[1][2*jp+1], ah[1][0], ah[1][1], ah[1][2], ah[1][3], bh[2], bh[3]);
                        mma_bf16(c[1][2*jp+1], ah[1][0], ah[1][1], ah[1][2], ah[1][3], bl[2], bl[3]);
                        mma_bf16(c[1][2*jp+1], al[1][0], al[1][1], al[1][2], al[1][3], bh[2], bh[3]);
                    }
                }
            }
        }
    }

    #pragma unroll
    for (int mi = 0; mi < 2; mi++) {
        if (!(mi == 0 ? act0 : act1)) continue;
        int rA = (int)m0 + wm * 32 + mi * 16 + g;
        int rB = rA + 8;
        #pragma unroll
        for (int ni = 0; ni < 8; ni++) {
            int n = (int)n0 + wn * 64 + ni * 8 + tg * 2;
            float b0v = bias[n], b1v = bias[n + 1];
            float v0 = (c[mi][ni][0] + b0v) * scale;
            float v1 = (c[mi][ni][1] + b1v) * scale;
            float v2 = (c[mi][ni][2] + b0v) * scale;
            float v3 = (c[mi][ni][3] + b1v) * scale;
            *(uint32_t*)(oh + (size_t)rA * DD + n) = packbf(v0, v1);
            *(uint32_t*)(ol + (size_t)rA * DD + n) = packbf(bflo(v0), bflo(v1));
            *(uint32_t*)(oh + (size_t)rB * DD + n) = packbf(v2, v3);
            *(uint32_t*)(ol + (size_t)rB * DD + n) = packbf(bflo(v2), bflo(v3));
        }
    }
}

// ---------------- output projection + residual + mask (HMMA, mask-skipped) ----------------
__global__ __launch_bounds__(256, 2) void out_mma_kernel(
    const float* __restrict__ bo, const float* __restrict__ nf,
    const float* __restrict__ masks, float* __restrict__ out) {
    extern __shared__ char sm[];
    uint32_t sbu = smem_u32(sm);
    int tid = threadIdx.x, lane = tid & 31, wid = tid >> 5;
    int g = lane >> 2, tg = lane & 3;
    int wm = wid & 3, wn = wid >> 2;
    size_t m0 = (size_t)blockIdx.x * 128, n0 = (size_t)blockIdx.y * 128;
    const __nv_bfloat16* Bh = g_wt_hi + (size_t)3 * DD * DD;
    const __nv_bfloat16* Bl = g_wt_lo + (size_t)3 * DD * DD;

    bool act0 = masks[m0 + wm * 32] > 0.f;
    bool act1 = masks[m0 + wm * 32 + 16] > 0.f;

    uint32_t aoff = (uint32_t)(((lane & 15) * 72 + (lane >> 4) * 8) * 2);
    uint32_t boff = (uint32_t)((((lane & 7) + ((lane >> 4) << 3)) * 72 + (lane & 8)) * 2);
    uint32_t aB0 = sbu + G_AHI + aoff + (uint32_t)(wm * 32) * 144;
    uint32_t aB1 = aB0 + 16 * 144;
    uint32_t bB  = sbu + G_BHI + boff + (uint32_t)(wn * 64) * 144;

    float c[2][8][4] = {};
    for (int kc = 0; kc < 4; kc++) {
        __syncthreads();
        #pragma unroll
        for (int it = 0; it < 4; it++) {
            int i = tid + it * 256;
            int row = i >> 3, seg = i & 7;
            int so = (row * 72 + seg * 8) * 2;
            size_t gb = (size_t)(n0 + row) * DD + kc * 64 + seg * 8;
            if (masks[m0 + (row & ~15)] > 0.f) {
                size_t ga = (size_t)(m0 + row) * DD + kc * 64 + seg * 8;
                float4 f0 = *(const float4*)(g_ctx + ga);
                float4 f1 = *(const float4*)(g_ctx + ga + 4);
                uint32_t ha, hb, la, lb, hc, hd, lc, ld;
                split4(f0, ha, hb, la, lb);
                split4(f1, hc, hd, lc, ld);
                *(uint4*)(sm + G_AHI + so) = make_uint4(ha, hb, hc, hd);
                *(uint4*)(sm + G_ALO + so) = make_uint4(la, lb, lc, ld);
            }
            *(uint4*)(sm + G_BHI + so) = *(const uint4*)(Bh + gb);
            *(uint4*)(sm + G_BLO + so) = *(const uint4*)(Bl + gb);
        }
        __syncthreads();
        if (act0 || act1) {
            #pragma unroll
            for (int kt = 0; kt < 4; kt++) {
                uint32_t ko = (uint32_t)(kt * 32);
                uint32_t ah[2][4], al[2][4];
                if (act0) {
                    ldsm4(aB0 + ko,                   ah[0][0], ah[0][1], ah[0][2], ah[0][3]);
                    ldsm4(aB0 + (G_ALO - G_AHI) + ko, al[0][0], al[0][1], al[0][2], al[0][3]);
                }
                if (act1) {
                    ldsm4(aB1 + ko,                   ah[1][0], ah[1][1], ah[1][2], ah[1][3]);
                    ldsm4(aB1 + (G_ALO - G_AHI) + ko, al[1][0], al[1][1], al[1][2], al[1][3]);
                }
                #pragma unroll
                for (int jp = 0; jp < 4; jp++) {
                    uint32_t bh[4], bl[4];
                    ldsm4(bB + jp * 2304 + ko,                   bh[0], bh[1], bh[2], bh[3]);
                    ldsm4(bB + (G_BLO - G_BHI) + jp * 2304 + ko, bl[0], bl[1], bl[2], bl[3]);
                    if (act0) {
                        mma_bf16(c[0][2*jp],   ah[0][0], ah[0][1], ah[0][2], ah[0][3], bh[0], bh[1]);
                        mma_bf16(c[0][2*jp],   ah[0][0], ah[0][1], ah[0][2], ah[0][3], bl[0], bl[1]);
                        mma_bf16(c[0][2*jp],   al[0][0], al[0][1], al[0][2], al[0][3], bh[0], bh[1]);
                        mma_bf16(c[0][2*jp+1], ah[0][0], ah[0][1], ah[0][2], ah[0][3], bh[2], bh[3]);
                        mma_bf16(c[0][2*jp+1], ah[0][0], ah[0][1], ah[0][2], ah[0][3], bl[2], bl[3]);
                        mma_bf16(c[0][2*jp+1], al[0][0], al[0][1], al[0][2], al[0][3], bh[2], bh[3]);
                    }
                    if (act1) {
                        mma_bf16(c[1][2*jp],   ah[1][0], ah[1][1], ah[1][2], ah[1][3], bh[0], bh[1]);
                        mma_bf16(c[1][2*jp],   ah[1][0], ah[1][1], ah[1][2], ah[1][3], bl[0], bl[1]);
                        mma_bf16(c[1][2*jp],   al[1][0], al[1][1], al[1][2], al[1][3], bh[0], bh[1]);
                        mma_bf16(c[1][2*jp+1], ah[1][0], ah[1][1], ah[1][2], ah[1][3], bh[2], bh[3]);
                        mma_bf16(c[1][2*jp+1], ah[1][0], ah[1][1], ah[1][2], ah[1][3], bl[2], bl[3]);
                        mma_bf16(c[1][2*jp+1], al[1][0], al[1][1], al[1][2], al[1][3], bh[2], bh[3]);
                    }
                }
            }
        }
    }

    // Unconditional stores: inactive frags have c=0 and mask=0 -> write exact zeros
    #pragma unroll
    for (int mi = 0; mi < 2; mi++) {
        int rA = (int)m0 + wm * 32 + mi * 16 + g;
        int rB = rA + 8;
        float mkA = masks[rA], mkB = masks[rB];
        #pragma unroll
        for (int ni = 0; ni < 8; ni++) {
            int n = (int)n0 + wn * 64 + ni * 8 + tg * 2;
            float b0v = bo[n], b1v = bo[n + 1];
            float2 resA = *(const float2*)(nf + (size_t)rA * DD + n);
            float2 resB = *(const float2*)(nf + (size_t)rB * DD + n);
            float2 oA = make_float2((c[mi][ni][0] + b0v + resA.x) * mkA,
                                    (c[mi][ni][1] + b1v + resA.y) * mkA);
            float2 oB = make_float2((c[mi][ni][2] + b0v + resB.x) * mkB,
                                    (c[mi][ni][3] + b1v + resB.y) * mkB);
            *(float2*)(out + (size_t)rA * DD + n) = oA;
            *(float2*)(out + (size_t)rB * DD + n) = oB;
        }
    }
}

// ---------------- per-(edge, head) attention: HMMA + ldmatrix(.trans V) + mask skipping ----------------
#define A_QH 0
#define A_QL 9216
#define A_KH 18432
#define A_KL 27648
#define A_VH 36864
#define A_VL 46080
#define A_KM 55296
#define A_QM 55552
#define A_SMEM 55808

__global__ __launch_bounds__(128, 4) void attn_mma_kernel(
    const long long* __restrict__ ei, const long long* __restrict__ et,
    const float* __restrict__ etw, const float* __restrict__ masks) {
    extern __shared__ char sm[];
    uint32_t sbu = smem_u32(sm);
    float* kmv = (float*)(sm + A_KM);
    float* qmv = (float*)(sm + A_QM);

    int e = blockIdx.x >> 2;
    int h = blockIdx.x & 3;
    int tid = threadIdx.x, lane = tid & 31, wid = tid >> 5;
    int g = lane >> 2, tg = lane & 3;

    bool is64 = true;
    #pragma unroll
    for (int i = 0; i < 16; i++) {
        long long v = ei[i];
        if (v < 0 || v >= NN) { is64 = false; break; }
    }
    const int* ei32 = (const int*)ei;
    const int* et32 = (const int*)et;
    int src = is64 ? (int)ei[e]      : ei32[e];
    int dst = is64 ? (int)ei[EE + e] : ei32[EE + e];
    int tt  = is64 ? (int)et[e]      : et32[e];
    float xw = etw[tt - 1];
    float sp = (xw > 20.f) ? xw : log1pf(__expf(xw));
    float ew = fminf(fmaxf(sp, 1e-6f), 1e6f);

    float md0 = masks[(size_t)dst * SS + lane], md1 = masks[(size_t)dst * SS + 32 + lane];
    float ms0 = masks[(size_t)src * SS + lane], ms1 = masks[(size_t)src * SS + 32 + lane];
    int len_dst = __popc(__ballot_sync(0xffffffffu, md0 > 0.f)) +
                  __popc(__ballot_sync(0xffffffffu, md1 > 0.f));
    int len_src = __popc(__ballot_sync(0xffffffffu, ms0 > 0.f)) +
                  __popc(__ballot_sync(0xffffffffu, ms1 > 0.f));
    int lq = (len_src + 15) & ~15;
    int lk = (len_dst + 15) & ~15;
    int jpmax = (((len_dst + 7) >> 3) + 1) >> 1;
    int ktmax = (len_dst + 15) >> 4;

    size_t qbase = ((size_t)src * SS) * DD + h * HDIM;
    size_t kbase = ((size_t)dst * SS) * DD + h * HDIM;
    for (int i = tid; i < 512; i += 128) {
        int row = i >> 3, seg = i & 7;
        int so = (row * 72 + seg * 8) * 2;
        size_t go = (size_t)row * DD + seg * 8;
        if (row < lq) {
            *(uint4*)(sm + A_QH + so) = *(const uint4*)(g_q_hi + qbase + go);
            *(uint4*)(sm + A_QL + so) = *(const uint4*)(g_q_lo + qbase + go);
        }
        if (row < lk) {
            *(uint4*)(sm + A_KH + so) = *(const uint4*)(g_k_hi + kbase + go);
            *(uint4*)(sm + A_KL + so) = *(const uint4*)(g_k_lo + kbase + go);
            *(uint4*)(sm + A_VH + so) = *(const uint4*)(g_v_hi + kbase + go);
            *(uint4*)(sm + A_VL + so) = *(const uint4*)(g_v_lo + kbase + go);
        }
    }
    if (tid < 32) { kmv[lane] = md0; kmv[32 + lane] = md1; }
    else if (tid < 64) { qmv[lane] = ms0; qmv[32 + lane] = ms1; }
    __syncthreads();

    int r0 = wid * 16;
    if (r0 >= len_src) return;

    uint32_t aoff = (uint32_t)(((lane & 15) * 72 + (lane >> 4) * 8) * 2);
    uint32_t boff = (uint32_t)((((lane & 7) + ((lane >> 4) << 3)) * 72 + (lane & 8)) * 2);
    uint32_t voff = (uint32_t)((lane & 15) * 144 + (lane >> 4) * 16);
    uint32_t qBH = sbu + A_QH + aoff + (uint32_t)r0 * 144;
    uint32_t qBL = qBH + (A_QL - A_QH);
    uint32_t kBH = sbu + A_KH + boff;
    uint32_t kBL = kBH + (A_KL - A_KH);
    uint32_t vBH = sbu + A_VH + voff;
    uint32_t vBL = vBH + (A_VL - A_VH);

    float sc[8][4] = {};
    #pragma unroll
    for (int kt = 0; kt < 4; kt++) {
        uint32_t ko = (uint32_t)(kt * 32);
        uint32_t ah[4], al[4];
        ldsm4(qBH + ko, ah[0], ah[1], ah[2], ah[3]);
        ldsm4(qBL + ko, al[0], al[1], al[2], al[3]);
        for (int jp = 0; jp < jpmax; jp++) {
            uint32_t bh[4], bl[4];
            ldsm4(kBH + jp * 2304 + ko, bh[0], bh[1], bh[2], bh[3]);
            ldsm4(kBL + jp * 2304 + ko, bl[0], bl[1], bl[2], bl[3]);
            mma_bf16(sc[2*jp],   ah[0], ah[1], ah[2], ah[3], bh[0], bh[1]);
            mma_bf16(sc[2*jp],   ah[0], ah[1], ah[2], ah[3], bl[0], bl[1]);
            mma_bf16(sc[2*jp],   al[0], al[1], al[2], al[3], bh[0], bh[1]);
            mma_bf16(sc[2*jp+1], ah[0], ah[1], ah[2], ah[3], bh[2], bh[3]);
            mma_bf16(sc[2*jp+1], ah[0], ah[1], ah[2], ah[3], bl[2], bl[3]);
            mma_bf16(sc[2*jp+1], al[0], al[1], al[2], al[3], bh[2], bh[3]);
        }
    }

    float kmr[8][2];
    #pragma unroll
    for (int jn = 0; jn < 8; jn++) {
        int col = jn * 8 + tg * 2;
        kmr[jn][0] = kmv[col];
        kmr[jn][1] = kmv[col + 1];
        sc[jn][0] = (kmr[jn][0] > 0.f) ? sc[jn][0] + ew : -1e30f;
        sc[jn][1] = (kmr[jn][1] > 0.f) ? sc[jn][1] + ew : -1e30f;
        sc[jn][2] = (kmr[jn][0] > 0.f) ? sc[jn][2] + ew : -1e30f;
        sc[jn][3] = (kmr[jn][1] > 0.f) ? sc[jn][3] + ew : -1e30f;
    }
    float mA = -1e30f, mB = -1e30f;
    #pragma unroll
    for (int jn = 0; jn < 8; jn++) {
        mA = fmaxf(mA, fmaxf(sc[jn][0], sc[jn][1]));
        mB = fmaxf(mB, fmaxf(sc[jn][2], sc[jn][3]));
    }
    mA = fmaxf(mA, __shfl_xor_sync(0xffffffffu, mA, 1));
    mA = fmaxf(mA, __shfl_xor_sync(0xffffffffu, mA, 2));
    mB = fmaxf(mB, __shfl_xor_sync(0xffffffffu, mB, 1));
    mB = fmaxf(mB, __shfl_xor_sync(0xffffffffu, mB, 2));
    float sA = 0.f, sB = 0.f;
    #pragma unroll
    for (int jn = 0; jn < 8; jn++) {
        sc[jn][0] = __expf(sc[jn][0] - mA); sA += sc[jn][0];
        sc[jn][1] = __expf(sc[jn][1] - mA); sA += sc[jn][1];
        sc[jn][2] = __expf(sc[jn][2] - mB); sB += sc[jn][2];
        sc[jn][3] = __expf(sc[jn][3] - mB); sB += sc[jn][3];
    }
    sA += __shfl_xor_sync(0xffffffffu, sA, 1);
    sA += __shfl_xor_sync(0xffffffffu, sA, 2);
    sB += __shfl_xor_sync(0xffffffffu, sB, 1);
    sB += __shfl_xor_sync(0xffffffffu, sB, 2);
    float iA = 1.0f / sA, iB = 1.0f / sB;
    #pragma unroll
    for (int jn = 0; jn < 8; jn++) {
        sc[jn][0] *= iA * kmr[jn][0];
        sc[jn][1] *= iA * kmr[jn][1];
        sc[jn][2] *= iB * kmr[jn][0];
        sc[jn][3] *= iB * kmr[jn][1];
    }

    uint32_t phi[4][4], plo[4][4];
    #pragma unroll
    for (int kt = 0; kt < 4; kt++) {
        int j0 = 2 * kt, j1 = 2 * kt + 1;
        phi[kt][0] = packbf(sc[j0][0], sc[j0][1]);
        phi[kt][1] = packbf(sc[j0][2], sc[j0][3]);
        phi[kt][2] = packbf(sc[j1][0], sc[j1][1]);
        phi[kt][3] = packbf(sc[j1][2], sc[j1][3]);
        plo[kt][0] = packbf(bflo(sc[j0][0]), bflo(sc[j0][1]));
        plo[kt][1] = packbf(bflo(sc[j0][2]), bflo(sc[j0][3]));
        plo[kt][2] = packbf(bflo(sc[j1][0]), bflo(sc[j1][1]));
        plo[kt][3] = packbf(bflo(sc[j1][2]), bflo(sc[j1][3]));
    }

    float o4[8][4] = {};
    for (int kt = 0; kt < ktmax; kt++) {
        uint32_t ko = (uint32_t)(kt * 2304);
        #pragma unroll
        for (int jp = 0; jp < 4; jp++) {
            uint32_t bh[4], bl[4];
            ldsm4t(vBH + ko + jp * 32, bh[0], bh[1], bh[2], bh[3]);
            ldsm4t(vBL + ko + jp * 32, bl[0], bl[1], bl[2], bl[3]);
            mma_bf16(o4[2*jp],   phi[kt][0], phi[kt][1], phi[kt][2], phi[kt][3], bh[0], bh[1]);
            mma_bf16(o4[2*jp],   phi[kt][0], phi[kt][1], phi[kt][2], phi[kt][3], bl[0], bl[1]);
            mma_bf16(o4[2*jp],   plo[kt][0], plo[kt][1], plo[kt][2], plo[kt][3], bh[0], bh[1]);
            mma_bf16(o4[2*jp+1], phi[kt][0], phi[kt][1], phi[kt][2], phi[kt][3], bh[2], bh[3]);
            mma_bf16(o4[2*jp+1], phi[kt][0], phi[kt][1], phi[kt][2], phi[kt][3], bl[2], bl[3]);
            mma_bf16(o4[2*jp+1], plo[kt][0], plo[kt][1], plo[kt][2], plo[kt][3], bh[2], bh[3]);
        }
    }

    int rowA = r0 + g, rowB = r0 + g + 8;
    float qmA = qmv[rowA], qmB = qmv[rowB];
    float* baseA = g_ctx + ((size_t)src * SS + rowA) * DD + h * HDIM;
    float* baseB = g_ctx + ((size_t)src * SS + rowB) * DD + h * HDIM;
    #pragma unroll
    for (int jn = 0; jn < 8; jn++) {
        int col = jn * 8 + tg * 2;
        if (qmA > 0.f) {
            atomicAdd(baseA + col,     o4[jn][0] * qmA);
            atomicAdd(baseA + col + 1, o4[jn][1] * qmA);
        }
        if (qmB > 0.f) {
            atomicAdd(baseB + col,     o4[jn][2] * qmB);
            atomicAdd(baseB + col + 1, o4[jn][3] * qmB);
        }
    }
}

extern "C" void kernel_launch(void* const* d_in, const int* in_sizes, int n_in,
                              void* d_out, int out_size) {
    const float* nf    = (const float*)d_in[0];
    const float* masks = (const float*)d_in[1];
    const float* lnw   = (const float*)d_in[2];
    const float* lnb   = (const float*)d_in[3];
    const float* wq    = (const float*)d_in[4];
    const float* bq    = (const float*)d_in[5];
    const float* wk    = (const float*)d_in[6];
    const float* bk    = (const float*)d_in[7];
    const float* wv    = (const float*)d_in[8];
    const float* bv    = (const float*)d_in[9];
    const float* wo    = (const float*)d_in[10];
    const float* bo    = (const float*)d_in[11];
    const float* etw   = (const float*)d_in[12];
    const long long* ei = (const long long*)d_in[13];
    const long long* et = (const long long*)d_in[14];
    float* out = (float*)d_out;

    cudaFuncSetAttribute(qkv_mma_kernel, cudaFuncAttributeMaxDynamicSharedMemorySize, G_SMEM);
    cudaFuncSetAttribute(out_mma_kernel, cudaFuncAttributeMaxDynamicSharedMemorySize, G_SMEM);
    cudaFuncSetAttribute(attn_mma_kernel, cudaFuncAttributeMaxDynamicSharedMemorySize, A_SMEM);

    zero_ctx_kernel<<<4096, 256>>>();
    ln_kernel<<<ROWS / 8, 256>>>(nf, lnw, lnb, masks);
    wconv_kernel<<<dim3(DD, 4), 256>>>(wq, wk, wv, wo);
    qkv_mma_kernel<<<dim3(6, ROWS / 128), 256, G_SMEM>>>(bq, bk, bv, masks);
    attn_mma_kernel<<<EE * HH, 128, A_SMEM>>>(ei, et, etw, masks);
    out_mma_kernel<<<dim3(ROWS / 128, DD / 128), 256, G_SMEM>>>(bo, nf, masks, out);
}